// round 1
// baseline (speedup 1.0000x reference)
#include <cuda_runtime.h>
#include <math.h>

#define B_ 8
#define N_ 9216
#define C_ 256
#define O_ 512
#define LN_EPS 1e-5f

// ---------------- scratch (device globals; no allocation allowed) ----------
__device__ float g_n1 [B_*N_*C_];   // LN(x1)  [b][n][c]
__device__ float g_n2 [B_*N_*C_];   // LN(x2)  [b][n][c]
__device__ float g_kqT[B_*C_*N_];   // n2 transposed [b][d][n]
__device__ float g_q  [B_*N_*C_];   // query softmax over channels [b][n][d]
__device__ float g_M  [B_*C_];      // per (b,d) max over n of kqT
__device__ float g_S  [B_*C_];      // per (b,d) sumexp
__device__ float g_ctx[B_*C_*C_];   // context, then combined attention (in place)
__device__ float g_WA [B_*O_*C_];   // reproj_w @ A   [b][o][e]

// ---------------- block reductions (256 threads) ---------------------------
__device__ __forceinline__ float blkSum(float v, float* sh) {
    #pragma unroll
    for (int o = 16; o > 0; o >>= 1) v += __shfl_down_sync(0xffffffffu, v, o);
    int w = threadIdx.x >> 5;
    if ((threadIdx.x & 31) == 0) sh[w] = v;
    __syncthreads();
    if (threadIdx.x < 32) {
        float x = (threadIdx.x < 8) ? sh[threadIdx.x] : 0.f;
        #pragma unroll
        for (int o = 4; o > 0; o >>= 1) x += __shfl_down_sync(0xffffffffu, x, o);
        if (threadIdx.x == 0) sh[0] = x;
    }
    __syncthreads();
    float r = sh[0];
    __syncthreads();
    return r;
}

__device__ __forceinline__ float blkMax(float v, float* sh) {
    #pragma unroll
    for (int o = 16; o > 0; o >>= 1) v = fmaxf(v, __shfl_down_sync(0xffffffffu, v, o));
    int w = threadIdx.x >> 5;
    if ((threadIdx.x & 31) == 0) sh[w] = v;
    __syncthreads();
    if (threadIdx.x < 32) {
        float x = (threadIdx.x < 8) ? sh[threadIdx.x] : -INFINITY;
        #pragma unroll
        for (int o = 4; o > 0; o >>= 1) x = fmaxf(x, __shfl_down_sync(0xffffffffu, x, o));
        if (threadIdx.x == 0) sh[0] = x;
    }
    __syncthreads();
    float r = sh[0];
    __syncthreads();
    return r;
}

// ---------------- Pass A: LayerNorm (optionally + channel softmax) ----------
// grid = B*N blocks, block = 256 threads (one row of C).
__global__ void ln_kernel(const float* __restrict__ x,
                          const float* __restrict__ w,
                          const float* __restrict__ b,
                          float* __restrict__ out,
                          float* __restrict__ qout) {
    __shared__ float sh[8];
    int row = blockIdx.x;
    int t = threadIdx.x;
    const float* xr = x + (size_t)row * C_;
    float v = xr[t];
    float s  = blkSum(v, sh);
    float s2 = blkSum(v * v, sh);
    float mu  = s * (1.f / C_);
    float var = s2 * (1.f / C_) - mu * mu;
    float ln = (v - mu) * rsqrtf(var + LN_EPS) * w[t] + b[t];
    out[(size_t)row * C_ + t] = ln;
    if (qout) {
        float m = blkMax(ln, sh);
        float e = __expf(ln - m);
        float se = blkSum(e, sh);
        qout[(size_t)row * C_ + t] = e / se;
    }
}

// ---------------- Pass T: transpose n2 [b][n][c] -> kqT [b][d][n] -----------
__global__ void transpose_kernel(const float* __restrict__ in, float* __restrict__ out) {
    __shared__ float tile[32][33];
    int b = blockIdx.z;
    int n0 = blockIdx.x * 32, c0 = blockIdx.y * 32;
    int x = threadIdx.x;
    #pragma unroll
    for (int y = threadIdx.y; y < 32; y += 8)
        tile[y][x] = in[(size_t)b * N_ * C_ + (size_t)(n0 + y) * C_ + c0 + x];
    __syncthreads();
    #pragma unroll
    for (int y = threadIdx.y; y < 32; y += 8)
        out[(size_t)b * C_ * N_ + (size_t)(c0 + y) * N_ + n0 + x] = tile[x][y];
}

// ---------------- Pass BC: per-(b,d) max + sumexp over N --------------------
// grid = B*C blocks, block = 256
__global__ void rowstat_kernel(const float* __restrict__ kqT,
                               float* __restrict__ Mv, float* __restrict__ Sv) {
    __shared__ float sh[8];
    int row = blockIdx.x;
    const float* r = kqT + (size_t)row * N_;
    float m = -INFINITY;
    for (int n = threadIdx.x; n < N_; n += 256) m = fmaxf(m, r[n]);
    m = blkMax(m, sh);
    float s = 0.f;
    for (int n = threadIdx.x; n < N_; n += 256) s += __expf(r[n] - m);
    s = blkSum(s, sh);
    if (threadIdx.x == 0) { Mv[row] = m; Sv[row] = s; }
}

// ---------------- generic 64x64 tiled NN GEMM -------------------------------
// C[m][n] = scale_row(m) * sum_k f(A[m][k]) * B[k][n]
// EXPA: f(v) = exp(v - Mrow[m]);  RSCALE: scale by 1/Srow[m]
template<int EXPA, int RSCALE>
__global__ void gemm64(const float* __restrict__ A, const float* __restrict__ B,
                       float* __restrict__ C,
                       int M, int Nn, int K,
                       size_t sA, size_t sB, size_t sC,
                       int lda, int ldb, int ldc,
                       const float* __restrict__ Mrow,
                       const float* __restrict__ Srow, int sStat) {
    int bz = blockIdx.z;
    const float* Ab = A + (size_t)bz * sA;
    const float* Bb = B + (size_t)bz * sB;
    float* Cb = C + (size_t)bz * sC;
    int m0 = blockIdx.y * 64, n0 = blockIdx.x * 64;

    __shared__ float sa[16][65];
    __shared__ float sb[16][64];
    __shared__ float sM[64];

    int t = threadIdx.x;
    if (EXPA && t < 64) sM[t] = Mrow[bz * sStat + m0 + t];
    int tx = t % 16, ty = t / 16;
    int r_ld = t / 16, kk_lda = t % 16;
    int c_ld = t % 64, kk_ldb = t / 64;

    float acc[4][4] = {};

    for (int k0 = 0; k0 < K; k0 += 16) {
        __syncthreads();
        #pragma unroll
        for (int it = 0; it < 4; it++) {
            float v = Ab[(size_t)(m0 + r_ld + 16 * it) * lda + k0 + kk_lda];
            if (EXPA) v = __expf(v - sM[r_ld + 16 * it]);
            sa[kk_lda][r_ld + 16 * it] = v;
            sb[kk_ldb + 4 * it][c_ld] = Bb[(size_t)(k0 + kk_ldb + 4 * it) * ldb + n0 + c_ld];
        }
        __syncthreads();
        #pragma unroll
        for (int kk = 0; kk < 16; kk++) {
            float av[4], bv[4];
            #pragma unroll
            for (int i = 0; i < 4; i++) av[i] = sa[kk][ty + 16 * i];
            #pragma unroll
            for (int j = 0; j < 4; j++) bv[j] = sb[kk][tx + 16 * j];
            #pragma unroll
            for (int i = 0; i < 4; i++)
                #pragma unroll
                for (int j = 0; j < 4; j++) acc[i][j] += av[i] * bv[j];
        }
    }

    #pragma unroll
    for (int i = 0; i < 4; i++) {
        int row = m0 + ty + 16 * i;
        float sc = 1.f;
        if (RSCALE) sc = 1.f / Srow[bz * sStat + row];
        #pragma unroll
        for (int j = 0; j < 4; j++)
            Cb[(size_t)row * ldc + n0 + tx + 16 * j] = acc[i][j] * sc;
    }
}

// ---------------- Pass E: combined top-k masked softmax ---------------------
// grid = B*C blocks (one context row), block = 256
__global__ void topk_kernel(float* __restrict__ ctx, const float* __restrict__ aw) {
    __shared__ float sc[C_];
    __shared__ float sh[8];
    int row = blockIdx.x;
    int t = threadIdx.x;
    float* base = ctx + (size_t)row * C_;
    float v = base[t];
    sc[t] = v;
    __syncthreads();

    int rank = 0;
    #pragma unroll 8
    for (int f = 0; f < C_; f++) {
        float vf = sc[f];
        rank += (vf > v) || (vf == v && f < t);
    }
    float m = blkMax(v, sh);
    float e = __expf(v - m);
    float z1 = blkSum(rank < 128 ? e : 0.f, sh);
    float z2 = blkSum(rank < 170 ? e : 0.f, sh);
    float z3 = blkSum(rank < 192 ? e : 0.f, sh);
    float z4 = blkSum(rank < 204 ? e : 0.f, sh);
    float coeff = 0.f;
    if (rank < 128) coeff += aw[0] / z1;
    if (rank < 170) coeff += aw[1] / z2;
    if (rank < 192) coeff += aw[2] / z3;
    if (rank < 204) coeff += aw[3] / z4;
    base[t] = e * coeff;
}

// ---------------- Pass F2: rp = q @ WA^T + bias, LN over 512, NCHW out ------
// grid = (N/32, B); block 256; thread tile 4 rows x 16 cols
__global__ void final_kernel(const float* __restrict__ q,
                             const float* __restrict__ WA,
                             const float* __restrict__ rbias,
                             const float* __restrict__ w2,
                             const float* __restrict__ b2,
                             float* __restrict__ out) {
    __shared__ float sm[16 * 513 + 16 * 33];   // swa[16][513] ++ sq[16][33]; reused as sout[256][33]
    float* swa = sm;
    float* sq  = sm + 16 * 513;

    int b = blockIdx.y;
    int n0 = blockIdx.x * 32;
    const float* qb  = q  + (size_t)b * N_ * C_;
    const float* WAb = WA + (size_t)b * O_ * C_;

    int t = threadIdx.x;
    int rg = t >> 5;      // 0..7  (warp id) -> rows rg*4 + i
    int cg = t & 31;      // lane  -> cols cg + 32*j

    float acc[4][16] = {};

    for (int k0 = 0; k0 < C_; k0 += 16) {
        __syncthreads();
        {
            int kk = t % 16, r0 = t / 16;
            #pragma unroll
            for (int it = 0; it < 2; it++) {
                int r = r0 + 16 * it;
                sq[kk * 33 + r] = qb[(size_t)(n0 + r) * C_ + k0 + kk];
            }
            #pragma unroll
            for (int it = 0; it < 32; it++) {
                int c = r0 + 16 * it;
                swa[kk * 513 + c] = WAb[(size_t)c * C_ + k0 + kk];
            }
        }
        __syncthreads();
        #pragma unroll 4
        for (int kk = 0; kk < 16; kk++) {
            float qa[4];
            #pragma unroll
            for (int i = 0; i < 4; i++) qa[i] = sq[kk * 33 + rg * 4 + i];
            #pragma unroll
            for (int j = 0; j < 16; j++) {
                float wv = swa[kk * 513 + cg + 32 * j];
                #pragma unroll
                for (int i = 0; i < 4; i++) acc[i][j] += qa[i] * wv;
            }
        }
    }

    // bias + LN stats (each warp owns 4 complete rows of 512)
    float mu[4], rs[4];
    #pragma unroll
    for (int i = 0; i < 4; i++) {
        float s = 0.f, s2 = 0.f;
        #pragma unroll
        for (int j = 0; j < 16; j++) {
            float x = acc[i][j] + rbias[cg + 32 * j];
            acc[i][j] = x;
            s += x; s2 += x * x;
        }
        #pragma unroll
        for (int o = 16; o > 0; o >>= 1) {
            s  += __shfl_xor_sync(0xffffffffu, s, o);
            s2 += __shfl_xor_sync(0xffffffffu, s2, o);
        }
        float m = s * (1.f / O_);
        float var = s2 * (1.f / O_) - m * m;
        mu[i] = m;
        rs[i] = rsqrtf(var + LN_EPS);
    }

    __syncthreads();           // everyone done with swa/sq
    float* sout = sm;          // [256][33]
    #pragma unroll
    for (int half = 0; half < 2; half++) {
        #pragma unroll
        for (int j = half * 8; j < half * 8 + 8; j++) {
            int col = cg + 32 * j;
            #pragma unroll
            for (int i = 0; i < 4; i++) {
                float x = (acc[i][j] - mu[i]) * rs[i] * w2[col] + b2[col];
                sout[(col - half * 256) * 33 + rg * 4 + i] = x;
            }
        }
        __syncthreads();
        #pragma unroll
        for (int it = 0; it < 32; it++) {
            int idx = t + 256 * it;
            int col = half * 256 + idx / 32;
            int nn = idx % 32;
            out[((size_t)b * O_ + col) * N_ + n0 + nn] = sout[(idx / 32) * 33 + nn];
        }
        __syncthreads();
    }
}

// ---------------- launch ----------------------------------------------------
extern "C" void kernel_launch(void* const* d_in, const int* in_sizes, int n_in,
                              void* d_out, int out_size) {
    const float* x1       = (const float*)d_in[0];
    const float* x2       = (const float*)d_in[1];
    const float* norm1_w  = (const float*)d_in[2];
    const float* norm1_b  = (const float*)d_in[3];
    const float* reproj_w = (const float*)d_in[4];
    const float* reproj_b = (const float*)d_in[5];
    const float* norm2_w  = (const float*)d_in[6];
    const float* norm2_b  = (const float*)d_in[7];
    const float* attn_w   = (const float*)d_in[8];
    float* out = (float*)d_out;

    float *n1, *n2, *kqT, *q, *M, *S, *ctx, *WA;
    cudaGetSymbolAddress((void**)&n1,  g_n1);
    cudaGetSymbolAddress((void**)&n2,  g_n2);
    cudaGetSymbolAddress((void**)&kqT, g_kqT);
    cudaGetSymbolAddress((void**)&q,   g_q);
    cudaGetSymbolAddress((void**)&M,   g_M);
    cudaGetSymbolAddress((void**)&S,   g_S);
    cudaGetSymbolAddress((void**)&ctx, g_ctx);
    cudaGetSymbolAddress((void**)&WA,  g_WA);

    // Pass A: LayerNorms (+ query softmax fused into x2 pass)
    ln_kernel<<<B_ * N_, 256>>>(x1, norm1_w, norm1_b, n1, nullptr);
    ln_kernel<<<B_ * N_, 256>>>(x2, norm1_w, norm1_b, n2, q);

    // Pass T: transpose n2 -> kqT
    transpose_kernel<<<dim3(N_ / 32, C_ / 32, B_), dim3(32, 8)>>>(n2, kqT);

    // Pass BC: per (b,d) softmax stats over N
    rowstat_kernel<<<B_ * C_, 256>>>(kqT, M, S);

    // Pass D: context = softmaxN(kqT) @ n1   [B,256,256]
    gemm64<1, 1><<<dim3(C_ / 64, C_ / 64, B_), 256>>>(
        kqT, n1, ctx, C_, C_, N_,
        (size_t)C_ * N_, (size_t)N_ * C_, (size_t)C_ * C_,
        N_, C_, C_, M, S, C_);

    // Pass E: combined 4-way top-k masked softmax (in place on ctx)
    topk_kernel<<<B_ * C_, 256>>>(ctx, attn_w);

    // Pass F1: WA = reproj_w @ A   [B,512,256]
    gemm64<0, 0><<<dim3(C_ / 64, O_ / 64, B_), 256>>>(
        reproj_w, ctx, WA, O_, C_, C_,
        (size_t)0, (size_t)C_ * C_, (size_t)O_ * C_,
        C_, C_, C_, nullptr, nullptr, 0);

    // Pass F2: rp = q @ WA^T + bias -> LN(512) -> [B,512,96,96]
    final_kernel<<<dim3(N_ / 32, B_), 256>>>(q, WA, reproj_b, norm2_w, norm2_b, out);
}

// round 2
// speedup vs baseline: 1.0020x; 1.0020x over previous
#include <cuda_runtime.h>
#include <math.h>

#define B_ 8
#define N_ 9216
#define C_ 256
#define O_ 512
#define LN_EPS 1e-5f

// ---------------- scratch (device globals; no allocation allowed) ----------
__device__ float g_n1 [B_*N_*C_];   // LN(x1)  [b][n][c]
__device__ float g_n2 [B_*N_*C_];   // LN(x2)  [b][n][c]
__device__ float g_kqT[B_*C_*N_];   // n2 transposed [b][d][n]
__device__ float g_q  [B_*N_*C_];   // query softmax over channels [b][n][d]
__device__ float g_M  [B_*C_];      // per (b,d) max over n of kqT
__device__ float g_S  [B_*C_];      // per (b,d) sumexp
__device__ float g_ctx[B_*C_*C_];   // context, then combined attention (in place)
__device__ float g_WA [B_*O_*C_];   // reproj_w @ A   [b][o][e]

// ---------------- block reductions (256 threads) ---------------------------
__device__ __forceinline__ float blkSum(float v, float* sh) {
    #pragma unroll
    for (int o = 16; o > 0; o >>= 1) v += __shfl_down_sync(0xffffffffu, v, o);
    int w = threadIdx.x >> 5;
    if ((threadIdx.x & 31) == 0) sh[w] = v;
    __syncthreads();
    if (threadIdx.x < 32) {
        float x = (threadIdx.x < 8) ? sh[threadIdx.x] : 0.f;
        #pragma unroll
        for (int o = 4; o > 0; o >>= 1) x += __shfl_down_sync(0xffffffffu, x, o);
        if (threadIdx.x == 0) sh[0] = x;
    }
    __syncthreads();
    float r = sh[0];
    __syncthreads();
    return r;
}

__device__ __forceinline__ float blkMax(float v, float* sh) {
    #pragma unroll
    for (int o = 16; o > 0; o >>= 1) v = fmaxf(v, __shfl_down_sync(0xffffffffu, v, o));
    int w = threadIdx.x >> 5;
    if ((threadIdx.x & 31) == 0) sh[w] = v;
    __syncthreads();
    if (threadIdx.x < 32) {
        float x = (threadIdx.x < 8) ? sh[threadIdx.x] : -INFINITY;
        #pragma unroll
        for (int o = 4; o > 0; o >>= 1) x = fmaxf(x, __shfl_down_sync(0xffffffffu, x, o));
        if (threadIdx.x == 0) sh[0] = x;
    }
    __syncthreads();
    float r = sh[0];
    __syncthreads();
    return r;
}

// ---------------- Pass A: LayerNorm (optionally + channel softmax) ----------
// grid = B*N blocks, block = 256 threads (one row of C).
__global__ void ln_kernel(const float* __restrict__ x,
                          const float* __restrict__ w,
                          const float* __restrict__ b,
                          float* __restrict__ out,
                          float* __restrict__ qout) {
    __shared__ float sh[8];
    int row = blockIdx.x;
    int t = threadIdx.x;
    const float* xr = x + (size_t)row * C_;
    float v = xr[t];
    float s  = blkSum(v, sh);
    float s2 = blkSum(v * v, sh);
    float mu  = s * (1.f / C_);
    float var = s2 * (1.f / C_) - mu * mu;
    float ln = (v - mu) * rsqrtf(var + LN_EPS) * w[t] + b[t];
    out[(size_t)row * C_ + t] = ln;
    if (qout) {
        float m = blkMax(ln, sh);
        float e = __expf(ln - m);
        float se = blkSum(e, sh);
        qout[(size_t)row * C_ + t] = e / se;
    }
}

// ---------------- Pass T: transpose n2 [b][n][c] -> kqT [b][d][n] -----------
__global__ void transpose_kernel(const float* __restrict__ in, float* __restrict__ out) {
    __shared__ float tile[32][33];
    int b = blockIdx.z;
    int n0 = blockIdx.x * 32, c0 = blockIdx.y * 32;
    int x = threadIdx.x;
    #pragma unroll
    for (int y = threadIdx.y; y < 32; y += 8)
        tile[y][x] = in[(size_t)b * N_ * C_ + (size_t)(n0 + y) * C_ + c0 + x];
    __syncthreads();
    #pragma unroll
    for (int y = threadIdx.y; y < 32; y += 8)
        out[(size_t)b * C_ * N_ + (size_t)(c0 + y) * N_ + n0 + x] = tile[x][y];
}

// ---------------- Pass BC: per-(b,d) max + sumexp over N --------------------
// grid = B*C blocks, block = 256
__global__ void rowstat_kernel(const float* __restrict__ kqT,
                               float* __restrict__ Mv, float* __restrict__ Sv) {
    __shared__ float sh[8];
    int row = blockIdx.x;
    const float* r = kqT + (size_t)row * N_;
    float m = -INFINITY;
    for (int n = threadIdx.x; n < N_; n += 256) m = fmaxf(m, r[n]);
    m = blkMax(m, sh);
    float s = 0.f;
    for (int n = threadIdx.x; n < N_; n += 256) s += __expf(r[n] - m);
    s = blkSum(s, sh);
    if (threadIdx.x == 0) { Mv[row] = m; Sv[row] = s; }
}

// ---------------- generic 64x64 tiled NN GEMM -------------------------------
// C[m][n] = scale_row(m) * sum_k f(A[m][k]) * B[k][n]
// EXPA: f(v) = exp(v - Mrow[m]);  RSCALE: scale by 1/Srow[m]
template<int EXPA, int RSCALE>
__global__ void gemm64(const float* __restrict__ A, const float* __restrict__ B,
                       float* __restrict__ C,
                       int M, int Nn, int K,
                       size_t sA, size_t sB, size_t sC,
                       int lda, int ldb, int ldc,
                       const float* __restrict__ Mrow,
                       const float* __restrict__ Srow, int sStat) {
    int bz = blockIdx.z;
    const float* Ab = A + (size_t)bz * sA;
    const float* Bb = B + (size_t)bz * sB;
    float* Cb = C + (size_t)bz * sC;
    int m0 = blockIdx.y * 64, n0 = blockIdx.x * 64;

    __shared__ float sa[16][65];
    __shared__ float sb[16][64];
    __shared__ float sM[64];

    int t = threadIdx.x;
    if (EXPA && t < 64) sM[t] = Mrow[bz * sStat + m0 + t];
    int tx = t % 16, ty = t / 16;
    int r_ld = t / 16, kk_lda = t % 16;
    int c_ld = t % 64, kk_ldb = t / 64;

    float acc[4][4] = {};

    for (int k0 = 0; k0 < K; k0 += 16) {
        __syncthreads();
        #pragma unroll
        for (int it = 0; it < 4; it++) {
            float v = Ab[(size_t)(m0 + r_ld + 16 * it) * lda + k0 + kk_lda];
            if (EXPA) v = __expf(v - sM[r_ld + 16 * it]);
            sa[kk_lda][r_ld + 16 * it] = v;
            sb[kk_ldb + 4 * it][c_ld] = Bb[(size_t)(k0 + kk_ldb + 4 * it) * ldb + n0 + c_ld];
        }
        __syncthreads();
        #pragma unroll
        for (int kk = 0; kk < 16; kk++) {
            float av[4], bv[4];
            #pragma unroll
            for (int i = 0; i < 4; i++) av[i] = sa[kk][ty + 16 * i];
            #pragma unroll
            for (int j = 0; j < 4; j++) bv[j] = sb[kk][tx + 16 * j];
            #pragma unroll
            for (int i = 0; i < 4; i++)
                #pragma unroll
                for (int j = 0; j < 4; j++) acc[i][j] += av[i] * bv[j];
        }
    }

    #pragma unroll
    for (int i = 0; i < 4; i++) {
        int row = m0 + ty + 16 * i;
        float sc = 1.f;
        if (RSCALE) sc = 1.f / Srow[bz * sStat + row];
        #pragma unroll
        for (int j = 0; j < 4; j++)
            Cb[(size_t)row * ldc + n0 + tx + 16 * j] = acc[i][j] * sc;
    }
}

// ---------------- Pass E: combined top-k masked softmax ---------------------
// grid = B*C blocks (one context row), block = 256
__global__ void topk_kernel(float* __restrict__ ctx, const float* __restrict__ aw) {
    __shared__ float sc[C_];
    __shared__ float sh[8];
    int row = blockIdx.x;
    int t = threadIdx.x;
    float* base = ctx + (size_t)row * C_;
    float v = base[t];
    sc[t] = v;
    __syncthreads();

    int rank = 0;
    #pragma unroll 8
    for (int f = 0; f < C_; f++) {
        float vf = sc[f];
        rank += (vf > v) || (vf == v && f < t);
    }
    float m = blkMax(v, sh);
    float e = __expf(v - m);
    float z1 = blkSum(rank < 128 ? e : 0.f, sh);
    float z2 = blkSum(rank < 170 ? e : 0.f, sh);
    float z3 = blkSum(rank < 192 ? e : 0.f, sh);
    float z4 = blkSum(rank < 204 ? e : 0.f, sh);
    float coeff = 0.f;
    if (rank < 128) coeff += aw[0] / z1;
    if (rank < 170) coeff += aw[1] / z2;
    if (rank < 192) coeff += aw[2] / z3;
    if (rank < 204) coeff += aw[3] / z4;
    base[t] = e * coeff;
}

// ---------------- Pass F2: rp = q @ WA^T + bias, LN over 512, NCHW out ------
// grid = (N/32, B); block 256; thread tile 4 rows x 16 cols
__global__ void final_kernel(const float* __restrict__ q,
                             const float* __restrict__ WA,
                             const float* __restrict__ rbias,
                             const float* __restrict__ w2,
                             const float* __restrict__ b2,
                             float* __restrict__ out) {
    __shared__ float sm[16 * 513 + 16 * 33];   // swa[16][513] ++ sq[16][33]; reused as sout[256][33]
    float* swa = sm;
    float* sq  = sm + 16 * 513;

    int b = blockIdx.y;
    int n0 = blockIdx.x * 32;
    const float* qb  = q  + (size_t)b * N_ * C_;
    const float* WAb = WA + (size_t)b * O_ * C_;

    int t = threadIdx.x;
    int rg = t >> 5;      // 0..7  (warp id) -> rows rg*4 + i
    int cg = t & 31;      // lane  -> cols cg + 32*j

    float acc[4][16] = {};

    for (int k0 = 0; k0 < C_; k0 += 16) {
        __syncthreads();
        {
            int kk = t % 16, r0 = t / 16;
            #pragma unroll
            for (int it = 0; it < 2; it++) {
                int r = r0 + 16 * it;
                sq[kk * 33 + r] = qb[(size_t)(n0 + r) * C_ + k0 + kk];
            }
            #pragma unroll
            for (int it = 0; it < 32; it++) {
                int c = r0 + 16 * it;
                swa[kk * 513 + c] = WAb[(size_t)c * C_ + k0 + kk];
            }
        }
        __syncthreads();
        #pragma unroll 4
        for (int kk = 0; kk < 16; kk++) {
            float qa[4];
            #pragma unroll
            for (int i = 0; i < 4; i++) qa[i] = sq[kk * 33 + rg * 4 + i];
            #pragma unroll
            for (int j = 0; j < 16; j++) {
                float wv = swa[kk * 513 + cg + 32 * j];
                #pragma unroll
                for (int i = 0; i < 4; i++) acc[i][j] += qa[i] * wv;
            }
        }
    }

    // bias + LN stats (each warp owns 4 complete rows of 512)
    float mu[4], rs[4];
    #pragma unroll
    for (int i = 0; i < 4; i++) {
        float s = 0.f, s2 = 0.f;
        #pragma unroll
        for (int j = 0; j < 16; j++) {
            float x = acc[i][j] + rbias[cg + 32 * j];
            acc[i][j] = x;
            s += x; s2 += x * x;
        }
        #pragma unroll
        for (int o = 16; o > 0; o >>= 1) {
            s  += __shfl_xor_sync(0xffffffffu, s, o);
            s2 += __shfl_xor_sync(0xffffffffu, s2, o);
        }
        float m = s * (1.f / O_);
        float var = s2 * (1.f / O_) - m * m;
        mu[i] = m;
        rs[i] = rsqrtf(var + LN_EPS);
    }

    __syncthreads();           // everyone done with swa/sq
    float* sout = sm;          // [256][33]
    #pragma unroll
    for (int half = 0; half < 2; half++) {
        #pragma unroll
        for (int j = half * 8; j < half * 8 + 8; j++) {
            int col = cg + 32 * j;
            #pragma unroll
            for (int i = 0; i < 4; i++) {
                float x = (acc[i][j] - mu[i]) * rs[i] * w2[col] + b2[col];
                sout[(col - half * 256) * 33 + rg * 4 + i] = x;
            }
        }
        __syncthreads();
        #pragma unroll
        for (int it = 0; it < 32; it++) {
            int idx = t + 256 * it;
            int col = half * 256 + idx / 32;
            int nn = idx % 32;
            out[((size_t)b * O_ + col) * N_ + n0 + nn] = sout[(idx / 32) * 33 + nn];
        }
        __syncthreads();
    }
}

// ---------------- launch ----------------------------------------------------
extern "C" void kernel_launch(void* const* d_in, const int* in_sizes, int n_in,
                              void* d_out, int out_size) {
    const float* x1       = (const float*)d_in[0];
    const float* x2       = (const float*)d_in[1];
    const float* norm1_w  = (const float*)d_in[2];
    const float* norm1_b  = (const float*)d_in[3];
    const float* reproj_w = (const float*)d_in[4];
    const float* reproj_b = (const float*)d_in[5];
    const float* norm2_w  = (const float*)d_in[6];
    const float* norm2_b  = (const float*)d_in[7];
    const float* attn_w   = (const float*)d_in[8];
    float* out = (float*)d_out;

    float *n1, *n2, *kqT, *q, *M, *S, *ctx, *WA;
    cudaGetSymbolAddress((void**)&n1,  g_n1);
    cudaGetSymbolAddress((void**)&n2,  g_n2);
    cudaGetSymbolAddress((void**)&kqT, g_kqT);
    cudaGetSymbolAddress((void**)&q,   g_q);
    cudaGetSymbolAddress((void**)&M,   g_M);
    cudaGetSymbolAddress((void**)&S,   g_S);
    cudaGetSymbolAddress((void**)&ctx, g_ctx);
    cudaGetSymbolAddress((void**)&WA,  g_WA);

    // Pass A: LayerNorms (+ query softmax fused into x2 pass)
    ln_kernel<<<B_ * N_, 256>>>(x1, norm1_w, norm1_b, n1, nullptr);
    ln_kernel<<<B_ * N_, 256>>>(x2, norm1_w, norm1_b, n2, q);

    // Pass T: transpose n2 -> kqT
    transpose_kernel<<<dim3(N_ / 32, C_ / 32, B_), dim3(32, 8)>>>(n2, kqT);

    // Pass BC: per (b,d) softmax stats over N
    rowstat_kernel<<<B_ * C_, 256>>>(kqT, M, S);

    // Pass D: context = softmaxN(kqT) @ n1   [B,256,256]
    gemm64<1, 1><<<dim3(C_ / 64, C_ / 64, B_), 256>>>(
        kqT, n1, ctx, C_, C_, N_,
        (size_t)C_ * N_, (size_t)N_ * C_, (size_t)C_ * C_,
        N_, C_, C_, M, S, C_);

    // Pass E: combined 4-way top-k masked softmax (in place on ctx)
    topk_kernel<<<B_ * C_, 256>>>(ctx, attn_w);

    // Pass F1: WA = reproj_w @ A   [B,512,256]
    gemm64<0, 0><<<dim3(C_ / 64, O_ / 64, B_), 256>>>(
        reproj_w, ctx, WA, O_, C_, C_,
        (size_t)0, (size_t)C_ * C_, (size_t)O_ * C_,
        C_, C_, C_, nullptr, nullptr, 0);

    // Pass F2: rp = q @ WA^T + bias -> LN(512) -> [B,512,96,96]
    final_kernel<<<dim3(N_ / 32, B_), 256>>>(q, WA, reproj_b, norm2_w, norm2_b, out);
}

// round 3
// speedup vs baseline: 2.4434x; 2.4385x over previous
#include <cuda_runtime.h>
#include <math.h>

#define B_ 8
#define N_ 9216
#define C_ 256
#define O_ 512
#define KS_ 16
#define CHK_ (N_/KS_)      // 576
#define NCH_ 36
#define CR_ (N_/NCH_)      // 256
#define LN_EPS 1e-5f

// ---------------- scratch ----------------------------------------------------
__device__ float g_n1 [B_*N_*C_];
__device__ float g_n2 [B_*N_*C_];
__device__ float g_q  [B_*N_*C_];
__device__ float g_pM [B_*NCH_*C_];
__device__ float g_pS [B_*NCH_*C_];
__device__ float g_M  [B_*C_];
__device__ float g_Si [B_*C_];
__device__ float g_ctxp[(size_t)KS_*B_*C_*C_];
__device__ float g_ctx[B_*C_*C_];
__device__ float g_WA [B_*O_*C_];

// ---------------- fast exp (FMA only, no MUFU) -------------------------------
__device__ __forceinline__ float fexp(float x) {
    float t = fmaf(x, 1.4426950408889634f, 12582912.0f);
    float n = t - 12582912.0f;
    int ni = __float_as_int(t) - 0x4B400000;
    float r = fmaf(n, -0.693359375f, x);
    r = fmaf(n, 2.12194440e-4f, r);
    float z = r * r;
    float p = 1.9875691500E-4f;
    p = fmaf(p, r, 1.3981999507E-3f);
    p = fmaf(p, r, 8.3334519073E-3f);
    p = fmaf(p, r, 4.1665795894E-2f);
    p = fmaf(p, r, 1.6666665459E-1f);
    p = fmaf(p, r, 5.0000001201E-1f);
    float res = fmaf(z, p, r) + 1.0f;
    res = __int_as_float(__float_as_int(res) + (ni << 23));
    return (x > -80.0f) ? res : 0.0f;
}

// ---------------- block reductions (256 threads) -----------------------------
__device__ __forceinline__ float blkSum(float v, float* sh) {
    #pragma unroll
    for (int o = 16; o > 0; o >>= 1) v += __shfl_down_sync(0xffffffffu, v, o);
    int w = threadIdx.x >> 5;
    if ((threadIdx.x & 31) == 0) sh[w] = v;
    __syncthreads();
    if (threadIdx.x < 32) {
        float x = (threadIdx.x < 8) ? sh[threadIdx.x] : 0.f;
        #pragma unroll
        for (int o = 4; o > 0; o >>= 1) x += __shfl_down_sync(0xffffffffu, x, o);
        if (threadIdx.x == 0) sh[0] = x;
    }
    __syncthreads();
    float r = sh[0];
    __syncthreads();
    return r;
}

__device__ __forceinline__ float blkMax(float v, float* sh) {
    #pragma unroll
    for (int o = 16; o > 0; o >>= 1) v = fmaxf(v, __shfl_down_sync(0xffffffffu, v, o));
    int w = threadIdx.x >> 5;
    if ((threadIdx.x & 31) == 0) sh[w] = v;
    __syncthreads();
    if (threadIdx.x < 32) {
        float x = (threadIdx.x < 8) ? sh[threadIdx.x] : -INFINITY;
        #pragma unroll
        for (int o = 4; o > 0; o >>= 1) x = fmaxf(x, __shfl_down_sync(0xffffffffu, x, o));
        if (threadIdx.x == 0) sh[0] = x;
    }
    __syncthreads();
    float r = sh[0];
    __syncthreads();
    return r;
}

// ---------------- Pass A: LayerNorm (+ optional channel softmax) -------------
__global__ void ln_kernel(const float* __restrict__ x,
                          const float* __restrict__ w,
                          const float* __restrict__ b,
                          float* __restrict__ out,
                          float* __restrict__ qout) {
    __shared__ float sh[8];
    int row = blockIdx.x;
    int t = threadIdx.x;
    float v = x[(size_t)row * C_ + t];
    float s  = blkSum(v, sh);
    float s2 = blkSum(v * v, sh);
    float mu  = s * (1.f / C_);
    float var = s2 * (1.f / C_) - mu * mu;
    float ln = (v - mu) * rsqrtf(var + LN_EPS) * w[t] + b[t];
    out[(size_t)row * C_ + t] = ln;
    if (qout) {
        float m = blkMax(ln, sh);
        float e = fexp(ln - m);
        float se = blkSum(e, sh);
        qout[(size_t)row * C_ + t] = e / se;
    }
}

// ---------------- column softmax stats over n2 (per b,d over N) --------------
__global__ void colstat1(const float* __restrict__ n2,
                         float* __restrict__ pM, float* __restrict__ pS) {
    int b = blockIdx.y, ch = blockIdx.x, t = threadIdx.x;
    const float* base = n2 + ((size_t)b * N_ + (size_t)ch * CR_) * C_ + t;
    float m = -1e30f;
    for (int r = 0; r < CR_; r++) m = fmaxf(m, base[(size_t)r * C_]);
    float s = 0.f;
    for (int r = 0; r < CR_; r++) s += fexp(base[(size_t)r * C_] - m);
    pM[((size_t)b * NCH_ + ch) * C_ + t] = m;
    pS[((size_t)b * NCH_ + ch) * C_ + t] = s;
}

__global__ void colstat2(const float* __restrict__ pM, const float* __restrict__ pS,
                         float* __restrict__ Mg, float* __restrict__ Si) {
    int b = blockIdx.x, t = threadIdx.x;
    float m = -1e30f;
    for (int c = 0; c < NCH_; c++)
        m = fmaxf(m, pM[((size_t)b * NCH_ + c) * C_ + t]);
    float s = 0.f;
    for (int c = 0; c < NCH_; c++)
        s += pS[((size_t)b * NCH_ + c) * C_ + t] * fexp(pM[((size_t)b * NCH_ + c) * C_ + t] - m);
    Mg[b * C_ + t] = m;
    Si[b * C_ + t] = 1.f / s;
}

// ---------------- context GEMM: split-K, exp(A) applied inline ---------------
// partial[ks][b][d][e] = sum_{n in chunk ks} exp(n2[b][n][d]-M[b][d]) * n1[b][n][e]
__global__ __launch_bounds__(256) void ctx_gemm(const float* __restrict__ n2,
                                                const float* __restrict__ n1g,
                                                const float* __restrict__ Mg,
                                                float* __restrict__ ctxp) {
    int bz = blockIdx.z;
    int b = bz / KS_, ks = bz % KS_;
    int m0 = blockIdx.y * 128, n0 = blockIdx.x * 128;
    const float* A  = n2  + (size_t)b * N_ * C_;
    const float* Bm = n1g + (size_t)b * N_ * C_;

    __shared__ float sa[16][132];
    __shared__ float sb[16][132];
    __shared__ float sM[128];

    int t = threadIdx.x;
    if (t < 128) sM[t] = Mg[b * C_ + m0 + t];
    int tx = t & 15, ty = t >> 4;

    float acc[8][8] = {};

    int kbase = ks * CHK_;
    for (int kt = 0; kt < CHK_; kt += 16) {
        __syncthreads();
        #pragma unroll
        for (int it = 0; it < 2; it++) {
            int idx = t + 256 * it;
            int kk = idx >> 5, m4 = (idx & 31) * 4;
            float4 va = *(const float4*)&A[(size_t)(kbase + kt + kk) * C_ + m0 + m4];
            float4 ea;
            ea.x = fexp(va.x - sM[m4]);
            ea.y = fexp(va.y - sM[m4 + 1]);
            ea.z = fexp(va.z - sM[m4 + 2]);
            ea.w = fexp(va.w - sM[m4 + 3]);
            *(float4*)&sa[kk][m4] = ea;
            *(float4*)&sb[kk][m4] = *(const float4*)&Bm[(size_t)(kbase + kt + kk) * C_ + n0 + m4];
        }
        __syncthreads();
        #pragma unroll
        for (int kk = 0; kk < 16; kk++) {
            float4 a0 = *(float4*)&sa[kk][ty * 4];
            float4 a1 = *(float4*)&sa[kk][64 + ty * 4];
            float4 b0 = *(float4*)&sb[kk][tx * 4];
            float4 b1 = *(float4*)&sb[kk][64 + tx * 4];
            float av[8] = {a0.x, a0.y, a0.z, a0.w, a1.x, a1.y, a1.z, a1.w};
            float bv[8] = {b0.x, b0.y, b0.z, b0.w, b1.x, b1.y, b1.z, b1.w};
            #pragma unroll
            for (int i = 0; i < 8; i++)
                #pragma unroll
                for (int j = 0; j < 8; j++)
                    acc[i][j] = fmaf(av[i], bv[j], acc[i][j]);
        }
    }

    float* dst = ctxp + ((size_t)ks * B_ + b) * C_ * C_;
    #pragma unroll
    for (int i = 0; i < 8; i++) {
        int row = m0 + ((i < 4) ? (ty * 4 + i) : (64 + ty * 4 + i - 4));
        #pragma unroll
        for (int h = 0; h < 2; h++) {
            float4 v = make_float4(acc[i][h * 4], acc[i][h * 4 + 1],
                                   acc[i][h * 4 + 2], acc[i][h * 4 + 3]);
            *(float4*)&dst[(size_t)row * C_ + n0 + h * 64 + tx * 4] = v;
        }
    }
}

// ---------------- combined 4-way top-k masked softmax ------------------------
__global__ void topk_kernel(const float* __restrict__ ctxp, float* __restrict__ ctx,
                            const float* __restrict__ aw, const float* __restrict__ Si) {
    __shared__ float sc[C_];
    __shared__ float sh[8];
    int row = blockIdx.x;             // b*C + d
    int b = row >> 8, d = row & 255;
    int t = threadIdx.x;
    float v = 0.f;
    #pragma unroll
    for (int ks = 0; ks < KS_; ks++)
        v += ctxp[(((size_t)ks * B_ + b) * C_ + d) * C_ + t];
    v *= Si[row];
    sc[t] = v;
    __syncthreads();

    int rank = 0;
    #pragma unroll 8
    for (int f = 0; f < C_; f++) {
        float vf = sc[f];
        rank += (vf > v) || (vf == v && f < t);
    }
    float m = blkMax(v, sh);
    float e = fexp(v - m);
    float z1 = blkSum(rank < 128 ? e : 0.f, sh);
    float z2 = blkSum(rank < 170 ? e : 0.f, sh);
    float z3 = blkSum(rank < 192 ? e : 0.f, sh);
    float z4 = blkSum(rank < 204 ? e : 0.f, sh);
    float coeff = 0.f;
    if (rank < 128) coeff += aw[0] / z1;
    if (rank < 170) coeff += aw[1] / z2;
    if (rank < 192) coeff += aw[2] / z3;
    if (rank < 204) coeff += aw[3] / z4;
    ctx[(size_t)row * C_ + t] = e * coeff;
}

// ---------------- small GEMM (F1): WA = reproj_w @ A -------------------------
__global__ void gemm64(const float* __restrict__ A, const float* __restrict__ B,
                       float* __restrict__ C,
                       int K, size_t sA, size_t sB, size_t sC,
                       int lda, int ldb, int ldc) {
    int bz = blockIdx.z;
    const float* Ab = A + (size_t)bz * sA;
    const float* Bb = B + (size_t)bz * sB;
    float* Cb = C + (size_t)bz * sC;
    int m0 = blockIdx.y * 64, n0 = blockIdx.x * 64;

    __shared__ float sa[16][65];
    __shared__ float sb[16][64];

    int t = threadIdx.x;
    int tx = t % 16, ty = t / 16;
    int r_ld = t / 16, kk_lda = t % 16;
    int c_ld = t % 64, kk_ldb = t / 64;

    float acc[4][4] = {};
    for (int k0 = 0; k0 < K; k0 += 16) {
        __syncthreads();
        #pragma unroll
        for (int it = 0; it < 4; it++) {
            sa[kk_lda][r_ld + 16 * it] = Ab[(size_t)(m0 + r_ld + 16 * it) * lda + k0 + kk_lda];
            sb[kk_ldb + 4 * it][c_ld] = Bb[(size_t)(k0 + kk_ldb + 4 * it) * ldb + n0 + c_ld];
        }
        __syncthreads();
        #pragma unroll
        for (int kk = 0; kk < 16; kk++) {
            float av[4], bv[4];
            #pragma unroll
            for (int i = 0; i < 4; i++) av[i] = sa[kk][ty + 16 * i];
            #pragma unroll
            for (int j = 0; j < 4; j++) bv[j] = sb[kk][tx + 16 * j];
            #pragma unroll
            for (int i = 0; i < 4; i++)
                #pragma unroll
                for (int j = 0; j < 4; j++) acc[i][j] = fmaf(av[i], bv[j], acc[i][j]);
        }
    }
    #pragma unroll
    for (int i = 0; i < 4; i++)
        #pragma unroll
        for (int j = 0; j < 4; j++)
            Cb[(size_t)(m0 + ty + 16 * i) * ldc + n0 + tx + 16 * j] = acc[i][j];
}

// ---------------- final: rp = q @ WA^T + bias -> LN(512) -> NCHW out ---------
// 64 n-rows x full 512 o-cols per block, 512 threads, 8x8 per thread.
__global__ __launch_bounds__(512, 1) void final_kernel(
        const float* __restrict__ q, const float* __restrict__ WA,
        const float* __restrict__ rbias, const float* __restrict__ w2g,
        const float* __restrict__ b2g, float* __restrict__ out) {
    __shared__ float sa[16][68];
    __shared__ float swa[16][516];
    __shared__ float redS[8][2][8];
    __shared__ float redQ[8][2][8];

    int b = blockIdx.y;
    int n0 = blockIdx.x * 64;
    const float* qb  = q  + (size_t)b * N_ * C_;
    const float* WAb = WA + (size_t)b * O_ * C_;

    int t = threadIdx.x;
    int ot = t & 63, nt = t >> 6;      // cols ot*4 / 256+ot*4, rows nt*8..+7
    int wh = (t >> 5) & 1;

    float acc[8][8] = {};

    for (int k0 = 0; k0 < C_; k0 += 16) {
        __syncthreads();
        if (t < 256) {
            int r = t >> 2, kg = (t & 3) * 4;
            float4 v = *(const float4*)&qb[(size_t)(n0 + r) * C_ + k0 + kg];
            sa[kg][r] = v.x; sa[kg + 1][r] = v.y; sa[kg + 2][r] = v.z; sa[kg + 3][r] = v.w;
        }
        #pragma unroll
        for (int it = 0; it < 4; it++) {
            int idx = t + 512 * it;
            int o = idx >> 2, kg = (idx & 3) * 4;
            float4 v = *(const float4*)&WAb[(size_t)o * C_ + k0 + kg];
            swa[kg][o] = v.x; swa[kg + 1][o] = v.y; swa[kg + 2][o] = v.z; swa[kg + 3][o] = v.w;
        }
        __syncthreads();
        #pragma unroll
        for (int kk = 0; kk < 16; kk++) {
            float4 a0 = *(float4*)&sa[kk][nt * 8];
            float4 a1 = *(float4*)&sa[kk][nt * 8 + 4];
            float4 c0 = *(float4*)&swa[kk][ot * 4];
            float4 c1 = *(float4*)&swa[kk][256 + ot * 4];
            float av[8] = {a0.x, a0.y, a0.z, a0.w, a1.x, a1.y, a1.z, a1.w};
            float bv[8] = {c0.x, c0.y, c0.z, c0.w, c1.x, c1.y, c1.z, c1.w};
            #pragma unroll
            for (int i = 0; i < 8; i++)
                #pragma unroll
                for (int j = 0; j < 8; j++)
                    acc[i][j] = fmaf(av[i], bv[j], acc[i][j]);
        }
    }

    // bias
    #pragma unroll
    for (int j = 0; j < 8; j++) {
        int o = (j < 4) ? (ot * 4 + j) : (256 + ot * 4 + j - 4);
        float bb = rbias[o];
        #pragma unroll
        for (int i = 0; i < 8; i++) acc[i][j] += bb;
    }

    // LN stats: rows owned by 64 threads (2 warps) each
    float mu[8], rs[8];
    #pragma unroll
    for (int i = 0; i < 8; i++) {
        float s = 0.f, s2 = 0.f;
        #pragma unroll
        for (int j = 0; j < 8; j++) { float x = acc[i][j]; s += x; s2 += x * x; }
        #pragma unroll
        for (int o = 16; o > 0; o >>= 1) {
            s  += __shfl_xor_sync(0xffffffffu, s, o);
            s2 += __shfl_xor_sync(0xffffffffu, s2, o);
        }
        if ((t & 31) == 0) { redS[nt][wh][i] = s; redQ[nt][wh][i] = s2; }
    }
    __syncthreads();
    #pragma unroll
    for (int i = 0; i < 8; i++) {
        float s  = redS[nt][0][i] + redS[nt][1][i];
        float s2 = redQ[nt][0][i] + redQ[nt][1][i];
        float m = s * (1.f / O_);
        float var = s2 * (1.f / O_) - m * m;
        mu[i] = m;
        rs[i] = rsqrtf(var + LN_EPS);
    }

    // write transposed: out[b][o][n], 32B-aligned float4 pairs per (o)
    #pragma unroll
    for (int j = 0; j < 8; j++) {
        int o = (j < 4) ? (ot * 4 + j) : (256 + ot * 4 + j - 4);
        float wv = w2g[o], bv2 = b2g[o];
        float4 lo, hi;
        lo.x = (acc[0][j] - mu[0]) * rs[0] * wv + bv2;
        lo.y = (acc[1][j] - mu[1]) * rs[1] * wv + bv2;
        lo.z = (acc[2][j] - mu[2]) * rs[2] * wv + bv2;
        lo.w = (acc[3][j] - mu[3]) * rs[3] * wv + bv2;
        hi.x = (acc[4][j] - mu[4]) * rs[4] * wv + bv2;
        hi.y = (acc[5][j] - mu[5]) * rs[5] * wv + bv2;
        hi.z = (acc[6][j] - mu[6]) * rs[6] * wv + bv2;
        hi.w = (acc[7][j] - mu[7]) * rs[7] * wv + bv2;
        float* op = out + ((size_t)b * O_ + o) * N_ + n0 + nt * 8;
        *(float4*)op = lo;
        *(float4*)(op + 4) = hi;
    }
}

// ---------------- launch -----------------------------------------------------
extern "C" void kernel_launch(void* const* d_in, const int* in_sizes, int n_in,
                              void* d_out, int out_size) {
    const float* x1       = (const float*)d_in[0];
    const float* x2       = (const float*)d_in[1];
    const float* norm1_w  = (const float*)d_in[2];
    const float* norm1_b  = (const float*)d_in[3];
    const float* reproj_w = (const float*)d_in[4];
    const float* reproj_b = (const float*)d_in[5];
    const float* norm2_w  = (const float*)d_in[6];
    const float* norm2_b  = (const float*)d_in[7];
    const float* attn_w   = (const float*)d_in[8];
    float* out = (float*)d_out;

    float *n1, *n2, *q, *pM, *pS, *M, *Si, *ctxp, *ctx, *WA;
    cudaGetSymbolAddress((void**)&n1,   g_n1);
    cudaGetSymbolAddress((void**)&n2,   g_n2);
    cudaGetSymbolAddress((void**)&q,    g_q);
    cudaGetSymbolAddress((void**)&pM,   g_pM);
    cudaGetSymbolAddress((void**)&pS,   g_pS);
    cudaGetSymbolAddress((void**)&M,    g_M);
    cudaGetSymbolAddress((void**)&Si,   g_Si);
    cudaGetSymbolAddress((void**)&ctxp, g_ctxp);
    cudaGetSymbolAddress((void**)&ctx,  g_ctx);
    cudaGetSymbolAddress((void**)&WA,   g_WA);

    ln_kernel<<<B_ * N_, 256>>>(x1, norm1_w, norm1_b, n1, nullptr);
    ln_kernel<<<B_ * N_, 256>>>(x2, norm1_w, norm1_b, n2, q);

    colstat1<<<dim3(NCH_, B_), 256>>>(n2, pM, pS);
    colstat2<<<B_, 256>>>(pM, pS, M, Si);

    ctx_gemm<<<dim3(2, 2, B_ * KS_), 256>>>(n2, n1, M, ctxp);

    topk_kernel<<<B_ * C_, 256>>>(ctxp, ctx, attn_w, Si);

    gemm64<<<dim3(C_ / 64, O_ / 64, B_), 256>>>(
        reproj_w, ctx, WA, C_,
        (size_t)0, (size_t)C_ * C_, (size_t)O_ * C_,
        C_, C_, C_);

    final_kernel<<<dim3(N_ / 64, B_), 512>>>(q, WA, reproj_b, norm2_w, norm2_b, out);
}

// round 4
// speedup vs baseline: 3.9186x; 1.6037x over previous
#include <cuda_runtime.h>
#include <math.h>

#define B_ 8
#define N_ 9216
#define C_ 256
#define O_ 512
#define KS_ 16
#define CHK_ (N_/KS_)      // 576
#define NCH_ 36
#define CR_ (N_/NCH_)      // 256
#define LN_EPS 1e-5f

typedef unsigned int uint;

// ---------------- scratch ----------------------------------------------------
__device__ float g_n1 [B_*N_*C_];
__device__ float g_n2 [B_*N_*C_];
__device__ float g_q  [B_*N_*C_];
__device__ float g_pM [B_*NCH_*C_];
__device__ float g_pS [B_*NCH_*C_];
__device__ float g_M  [B_*C_];
__device__ float g_Si [B_*C_];
__device__ float g_ctxp[(size_t)KS_*B_*C_*C_];
__device__ float g_ctx[B_*C_*C_];
__device__ float g_WA [B_*O_*C_];

// ---------------- fast exp (FMA only) ----------------------------------------
__device__ __forceinline__ float fexp(float x) {
    float t = fmaf(x, 1.4426950408889634f, 12582912.0f);
    float n = t - 12582912.0f;
    int ni = __float_as_int(t) - 0x4B400000;
    float r = fmaf(n, -0.693359375f, x);
    r = fmaf(n, 2.12194440e-4f, r);
    float z = r * r;
    float p = 1.9875691500E-4f;
    p = fmaf(p, r, 1.3981999507E-3f);
    p = fmaf(p, r, 8.3334519073E-3f);
    p = fmaf(p, r, 4.1665795894E-2f);
    p = fmaf(p, r, 1.6666665459E-1f);
    p = fmaf(p, r, 5.0000001201E-1f);
    float res = fmaf(z, p, r) + 1.0f;
    res = __int_as_float(__float_as_int(res) + (ni << 23));
    return (x > -80.0f) ? res : 0.0f;
}

// ---------------- tf32 helpers -----------------------------------------------
__device__ __forceinline__ uint tf32c(float f) {
    uint r;
    asm("cvt.rna.tf32.f32 %0, %1;" : "=r"(r) : "f"(f));
    return r;
}
__device__ __forceinline__ uint4 tf32c4(float4 v) {
    uint4 u;
    u.x = tf32c(v.x); u.y = tf32c(v.y); u.z = tf32c(v.z); u.w = tf32c(v.w);
    return u;
}
__device__ __forceinline__ void mma8(float4& d, const uint* a, const uint* b) {
    asm volatile("mma.sync.aligned.m16n8k8.row.col.f32.tf32.tf32.f32 "
        "{%0,%1,%2,%3}, {%4,%5,%6,%7}, {%8,%9}, {%0,%1,%2,%3};"
        : "+f"(d.x), "+f"(d.y), "+f"(d.z), "+f"(d.w)
        : "r"(a[0]), "r"(a[1]), "r"(a[2]), "r"(a[3]), "r"(b[0]), "r"(b[1]));
}

// ---------------- block reductions (256 threads) -----------------------------
__device__ __forceinline__ float blkSum(float v, float* sh) {
    #pragma unroll
    for (int o = 16; o > 0; o >>= 1) v += __shfl_down_sync(0xffffffffu, v, o);
    int w = threadIdx.x >> 5;
    if ((threadIdx.x & 31) == 0) sh[w] = v;
    __syncthreads();
    if (threadIdx.x < 32) {
        float x = (threadIdx.x < 8) ? sh[threadIdx.x] : 0.f;
        #pragma unroll
        for (int o = 4; o > 0; o >>= 1) x += __shfl_down_sync(0xffffffffu, x, o);
        if (threadIdx.x == 0) sh[0] = x;
    }
    __syncthreads();
    float r = sh[0];
    __syncthreads();
    return r;
}
__device__ __forceinline__ float blkMax(float v, float* sh) {
    #pragma unroll
    for (int o = 16; o > 0; o >>= 1) v = fmaxf(v, __shfl_down_sync(0xffffffffu, v, o));
    int w = threadIdx.x >> 5;
    if ((threadIdx.x & 31) == 0) sh[w] = v;
    __syncthreads();
    if (threadIdx.x < 32) {
        float x = (threadIdx.x < 8) ? sh[threadIdx.x] : -INFINITY;
        #pragma unroll
        for (int o = 4; o > 0; o >>= 1) x = fmaxf(x, __shfl_down_sync(0xffffffffu, x, o));
        if (threadIdx.x == 0) sh[0] = x;
    }
    __syncthreads();
    float r = sh[0];
    __syncthreads();
    return r;
}

// ---------------- LayerNorm, warp-per-row (+ optional channel softmax) -------
__global__ void ln_kernel(const float* __restrict__ x,
                          const float* __restrict__ w,
                          const float* __restrict__ b,
                          float* __restrict__ out,
                          float* __restrict__ qout) {
    int warp = threadIdx.x >> 5, lane = threadIdx.x & 31;
    size_t row = (size_t)blockIdx.x * 8 + warp;
    const float4* xr = (const float4*)(x + row * C_);
    float4 v0 = xr[lane], v1 = xr[lane + 32];
    float s  = v0.x + v0.y + v0.z + v0.w + v1.x + v1.y + v1.z + v1.w;
    float s2 = v0.x*v0.x + v0.y*v0.y + v0.z*v0.z + v0.w*v0.w
             + v1.x*v1.x + v1.y*v1.y + v1.z*v1.z + v1.w*v1.w;
    #pragma unroll
    for (int o = 16; o > 0; o >>= 1) {
        s  += __shfl_xor_sync(0xffffffffu, s, o);
        s2 += __shfl_xor_sync(0xffffffffu, s2, o);
    }
    float mu = s * (1.f / C_);
    float rsd = rsqrtf(s2 * (1.f / C_) - mu * mu + LN_EPS);
    float4 w0 = ((const float4*)w)[lane], w1 = ((const float4*)w)[lane + 32];
    float4 b0 = ((const float4*)b)[lane], b1 = ((const float4*)b)[lane + 32];
    float4 l0, l1;
    l0.x = (v0.x - mu) * rsd * w0.x + b0.x;
    l0.y = (v0.y - mu) * rsd * w0.y + b0.y;
    l0.z = (v0.z - mu) * rsd * w0.z + b0.z;
    l0.w = (v0.w - mu) * rsd * w0.w + b0.w;
    l1.x = (v1.x - mu) * rsd * w1.x + b1.x;
    l1.y = (v1.y - mu) * rsd * w1.y + b1.y;
    l1.z = (v1.z - mu) * rsd * w1.z + b1.z;
    l1.w = (v1.w - mu) * rsd * w1.w + b1.w;
    float4* outr = (float4*)(out + row * C_);
    outr[lane] = l0; outr[lane + 32] = l1;
    if (qout) {
        float m = fmaxf(fmaxf(fmaxf(l0.x, l0.y), fmaxf(l0.z, l0.w)),
                        fmaxf(fmaxf(l1.x, l1.y), fmaxf(l1.z, l1.w)));
        #pragma unroll
        for (int o = 16; o > 0; o >>= 1) m = fmaxf(m, __shfl_xor_sync(0xffffffffu, m, o));
        float4 e0, e1;
        e0.x = fexp(l0.x - m); e0.y = fexp(l0.y - m); e0.z = fexp(l0.z - m); e0.w = fexp(l0.w - m);
        e1.x = fexp(l1.x - m); e1.y = fexp(l1.y - m); e1.z = fexp(l1.z - m); e1.w = fexp(l1.w - m);
        float se = e0.x + e0.y + e0.z + e0.w + e1.x + e1.y + e1.z + e1.w;
        #pragma unroll
        for (int o = 16; o > 0; o >>= 1) se += __shfl_xor_sync(0xffffffffu, se, o);
        float inv = 1.f / se;
        e0.x *= inv; e0.y *= inv; e0.z *= inv; e0.w *= inv;
        e1.x *= inv; e1.y *= inv; e1.z *= inv; e1.w *= inv;
        float4* qr = (float4*)(qout + row * C_);
        qr[lane] = e0; qr[lane + 32] = e1;
    }
}

// ---------------- column softmax stats over n2 -------------------------------
__global__ void colstat1(const float* __restrict__ n2,
                         float* __restrict__ pM, float* __restrict__ pS) {
    int b = blockIdx.y, ch = blockIdx.x, t = threadIdx.x;
    const float* base = n2 + ((size_t)b * N_ + (size_t)ch * CR_) * C_ + t;
    float m = -1e30f;
    for (int r = 0; r < CR_; r++) m = fmaxf(m, base[(size_t)r * C_]);
    float s = 0.f;
    for (int r = 0; r < CR_; r++) s += fexp(base[(size_t)r * C_] - m);
    pM[((size_t)b * NCH_ + ch) * C_ + t] = m;
    pS[((size_t)b * NCH_ + ch) * C_ + t] = s;
}
__global__ void colstat2(const float* __restrict__ pM, const float* __restrict__ pS,
                         float* __restrict__ Mg, float* __restrict__ Si) {
    int b = blockIdx.x, t = threadIdx.x;
    float m = -1e30f;
    for (int c = 0; c < NCH_; c++)
        m = fmaxf(m, pM[((size_t)b * NCH_ + c) * C_ + t]);
    float s = 0.f;
    for (int c = 0; c < NCH_; c++)
        s += pS[((size_t)b * NCH_ + c) * C_ + t] * fexp(pM[((size_t)b * NCH_ + c) * C_ + t] - m);
    Mg[b * C_ + t] = m;
    Si[b * C_ + t] = 1.f / s;
}

// ---------------- context GEMM: tf32 mma, split-K ----------------------------
__global__ __launch_bounds__(256) void ctx_gemm(const float* __restrict__ n2,
                                                const float* __restrict__ n1g,
                                                const float* __restrict__ Mg,
                                                float* __restrict__ ctxp) {
    int bz = blockIdx.z;
    int b = bz / KS_, sk = bz % KS_;
    int m0 = blockIdx.y * 128, n0 = blockIdx.x * 128;
    const float* A  = n2  + (size_t)b * N_ * C_;
    const float* Bm = n1g + (size_t)b * N_ * C_;

    __shared__ uint sa[16][136];
    __shared__ uint sb[16][136];
    __shared__ float sM[128];

    int t = threadIdx.x;
    if (t < 128) sM[t] = Mg[b * C_ + m0 + t];
    int warp = t >> 5, lane = t & 31, g = lane >> 2, tg = lane & 3;
    int wm = (warp >> 2) * 64, wn = (warp & 3) * 32;

    float4 acc[4][4];
    #pragma unroll
    for (int i = 0; i < 4; i++)
        #pragma unroll
        for (int j = 0; j < 4; j++) acc[i][j] = make_float4(0.f, 0.f, 0.f, 0.f);

    int kbase = sk * CHK_;
    for (int kt = 0; kt < CHK_; kt += 16) {
        __syncthreads();
        #pragma unroll
        for (int it = 0; it < 2; it++) {
            int idx = t + 256 * it;
            int kk = idx >> 5, m4 = (idx & 31) * 4;
            float4 va = *(const float4*)&A[(size_t)(kbase + kt + kk) * C_ + m0 + m4];
            uint4 ua;
            ua.x = tf32c(fexp(va.x - sM[m4]));
            ua.y = tf32c(fexp(va.y - sM[m4 + 1]));
            ua.z = tf32c(fexp(va.z - sM[m4 + 2]));
            ua.w = tf32c(fexp(va.w - sM[m4 + 3]));
            *(uint4*)&sa[kk][m4] = ua;
            float4 vb = *(const float4*)&Bm[(size_t)(kbase + kt + kk) * C_ + n0 + m4];
            *(uint4*)&sb[kk][m4] = tf32c4(vb);
        }
        __syncthreads();
        #pragma unroll
        for (int ks = 0; ks < 16; ks += 8) {
            uint afr[4][4], bfr[4][2];
            #pragma unroll
            for (int mt = 0; mt < 4; mt++) {
                int m = wm + mt * 16 + g;
                afr[mt][0] = sa[ks + tg][m];
                afr[mt][1] = sa[ks + tg][m + 8];
                afr[mt][2] = sa[ks + tg + 4][m];
                afr[mt][3] = sa[ks + tg + 4][m + 8];
            }
            #pragma unroll
            for (int nt = 0; nt < 4; nt++) {
                int n = wn + nt * 8 + g;
                bfr[nt][0] = sb[ks + tg][n];
                bfr[nt][1] = sb[ks + tg + 4][n];
            }
            #pragma unroll
            for (int mt = 0; mt < 4; mt++)
                #pragma unroll
                for (int nt = 0; nt < 4; nt++)
                    mma8(acc[mt][nt], afr[mt], bfr[nt]);
        }
    }

    float* dst = ctxp + ((size_t)sk * B_ + b) * C_ * C_;
    #pragma unroll
    for (int mt = 0; mt < 4; mt++) {
        int row = m0 + wm + mt * 16 + g;
        #pragma unroll
        for (int nt = 0; nt < 4; nt++) {
            int col = n0 + wn + nt * 8 + tg * 2;
            *(float2*)&dst[(size_t)row * C_ + col] = make_float2(acc[mt][nt].x, acc[mt][nt].y);
            *(float2*)&dst[(size_t)(row + 8) * C_ + col] = make_float2(acc[mt][nt].z, acc[mt][nt].w);
        }
    }
}

// ---------------- combined 4-way top-k masked softmax ------------------------
__global__ void topk_kernel(const float* __restrict__ ctxp, float* __restrict__ ctx,
                            const float* __restrict__ aw, const float* __restrict__ Si) {
    __shared__ float sc[C_];
    __shared__ float sh[8];
    int row = blockIdx.x;
    int b = row >> 8, d = row & 255;
    int t = threadIdx.x;
    float v = 0.f;
    #pragma unroll
    for (int sk = 0; sk < KS_; sk++)
        v += ctxp[(((size_t)sk * B_ + b) * C_ + d) * C_ + t];
    v *= Si[row];
    sc[t] = v;
    __syncthreads();
    int rank = 0;
    #pragma unroll 8
    for (int f = 0; f < C_; f++) {
        float vf = sc[f];
        rank += (vf > v) || (vf == v && f < t);
    }
    float m = blkMax(v, sh);
    float e = fexp(v - m);
    float z1 = blkSum(rank < 128 ? e : 0.f, sh);
    float z2 = blkSum(rank < 170 ? e : 0.f, sh);
    float z3 = blkSum(rank < 192 ? e : 0.f, sh);
    float z4 = blkSum(rank < 204 ? e : 0.f, sh);
    float coeff = 0.f;
    if (rank < 128) coeff += aw[0] / z1;
    if (rank < 170) coeff += aw[1] / z2;
    if (rank < 192) coeff += aw[2] / z3;
    if (rank < 204) coeff += aw[3] / z4;
    ctx[(size_t)row * C_ + t] = e * coeff;
}

// ---------------- small GEMM (F1): WA = reproj_w @ A -------------------------
__global__ void gemm64(const float* __restrict__ A, const float* __restrict__ B,
                       float* __restrict__ C,
                       int K, size_t sA, size_t sB, size_t sC,
                       int lda, int ldb, int ldc) {
    int bz = blockIdx.z;
    const float* Ab = A + (size_t)bz * sA;
    const float* Bb = B + (size_t)bz * sB;
    float* Cb = C + (size_t)bz * sC;
    int m0 = blockIdx.y * 64, n0 = blockIdx.x * 64;
    __shared__ float sa[16][65];
    __shared__ float sb[16][64];
    int t = threadIdx.x;
    int tx = t % 16, ty = t / 16;
    int r_ld = t / 16, kk_lda = t % 16;
    int c_ld = t % 64, kk_ldb = t / 64;
    float acc[4][4] = {};
    for (int k0 = 0; k0 < K; k0 += 16) {
        __syncthreads();
        #pragma unroll
        for (int it = 0; it < 4; it++) {
            sa[kk_lda][r_ld + 16 * it] = Ab[(size_t)(m0 + r_ld + 16 * it) * lda + k0 + kk_lda];
            sb[kk_ldb + 4 * it][c_ld] = Bb[(size_t)(k0 + kk_ldb + 4 * it) * ldb + n0 + c_ld];
        }
        __syncthreads();
        #pragma unroll
        for (int kk = 0; kk < 16; kk++) {
            float av[4], bv[4];
            #pragma unroll
            for (int i = 0; i < 4; i++) av[i] = sa[kk][ty + 16 * i];
            #pragma unroll
            for (int j = 0; j < 4; j++) bv[j] = sb[kk][tx + 16 * j];
            #pragma unroll
            for (int i = 0; i < 4; i++)
                #pragma unroll
                for (int j = 0; j < 4; j++) acc[i][j] = fmaf(av[i], bv[j], acc[i][j]);
        }
    }
    #pragma unroll
    for (int i = 0; i < 4; i++)
        #pragma unroll
        for (int j = 0; j < 4; j++)
            Cb[(size_t)(m0 + ty + 16 * i) * ldc + n0 + tx + 16 * j] = acc[i][j];
}

// ---------------- final: rp = q @ WA^T (tf32 mma) + bias -> LN -> NCHW -------
#define SQW 12
#define POOLW (128 * 68)    // sout[128][68] floats; >= 64*12 + 512*12
__global__ __launch_bounds__(512) void final_kernel(
        const float* __restrict__ q, const float* __restrict__ WA,
        const float* __restrict__ rbias, const float* __restrict__ w2g,
        const float* __restrict__ b2g, float* __restrict__ out) {
    __shared__ __align__(16) uint pool[POOLW];
    __shared__ float redS[16][64];
    __shared__ float redQ[16][64];
    __shared__ float muS[64], rsS[64];
    uint* sq  = pool;             // [64][SQW]
    uint* swa = pool + 64 * SQW;  // [512][SQW]
    float* sout = (float*)pool;   // [128][68]

    int bb = blockIdx.y;
    int n0 = blockIdx.x * 64;
    const float* qb  = q  + (size_t)bb * N_ * C_;
    const float* WAb = WA + (size_t)bb * O_ * C_;

    int t = threadIdx.x, warp = t >> 5, lane = t & 31, g = lane >> 2, tg = lane & 3;
    int o0 = warp * 32;

    float4 acc[4][4];
    #pragma unroll
    for (int i = 0; i < 4; i++)
        #pragma unroll
        for (int j = 0; j < 4; j++) acc[i][j] = make_float4(0.f, 0.f, 0.f, 0.f);

    for (int k0 = 0; k0 < C_; k0 += 8) {
        __syncthreads();
        if (t < 128) {
            int r = t >> 1, kg = (t & 1) * 4;
            float4 v = *(const float4*)&qb[(size_t)(n0 + r) * C_ + k0 + kg];
            *(uint4*)&sq[r * SQW + kg] = tf32c4(v);
        }
        #pragma unroll
        for (int it = 0; it < 2; it++) {
            int idx = t + 512 * it;
            int o = idx >> 1, kg = (idx & 1) * 4;
            float4 v = *(const float4*)&WAb[(size_t)o * C_ + k0 + kg];
            *(uint4*)&swa[o * SQW + kg] = tf32c4(v);
        }
        __syncthreads();
        uint afr[4][4], bfr[4][2];
        #pragma unroll
        for (int mt = 0; mt < 4; mt++) {
            int r1 = mt * 16 + g;
            afr[mt][0] = sq[r1 * SQW + tg];
            afr[mt][1] = sq[(r1 + 8) * SQW + tg];
            afr[mt][2] = sq[r1 * SQW + tg + 4];
            afr[mt][3] = sq[(r1 + 8) * SQW + tg + 4];
        }
        #pragma unroll
        for (int nt = 0; nt < 4; nt++) {
            int o = o0 + nt * 8 + g;
            bfr[nt][0] = swa[o * SQW + tg];
            bfr[nt][1] = swa[o * SQW + tg + 4];
        }
        #pragma unroll
        for (int mt = 0; mt < 4; mt++)
            #pragma unroll
            for (int nt = 0; nt < 4; nt++)
                mma8(acc[mt][nt], afr[mt], bfr[nt]);
    }

    // bias
    #pragma unroll
    for (int nt = 0; nt < 4; nt++) {
        int o = o0 + nt * 8 + tg * 2;
        float2 rb = *(const float2*)&rbias[o];
        #pragma unroll
        for (int mt = 0; mt < 4; mt++) {
            acc[mt][nt].x += rb.x; acc[mt][nt].y += rb.y;
            acc[mt][nt].z += rb.x; acc[mt][nt].w += rb.y;
        }
    }

    // LN stats
    #pragma unroll
    for (int mt = 0; mt < 4; mt++) {
        float sA = 0.f, qA = 0.f, sB = 0.f, qB = 0.f;
        #pragma unroll
        for (int nt = 0; nt < 4; nt++) {
            float4 a = acc[mt][nt];
            sA += a.x + a.y; qA += a.x * a.x + a.y * a.y;
            sB += a.z + a.w; qB += a.z * a.z + a.w * a.w;
        }
        #pragma unroll
        for (int o = 1; o <= 2; o <<= 1) {
            sA += __shfl_xor_sync(0xffffffffu, sA, o);
            qA += __shfl_xor_sync(0xffffffffu, qA, o);
            sB += __shfl_xor_sync(0xffffffffu, sB, o);
            qB += __shfl_xor_sync(0xffffffffu, qB, o);
        }
        if (tg == 0) {
            redS[warp][mt * 16 + g] = sA;
            redQ[warp][mt * 16 + g] = qA;
            redS[warp][mt * 16 + g + 8] = sB;
            redQ[warp][mt * 16 + g + 8] = qB;
        }
    }
    __syncthreads();
    if (t < 64) {
        float s = 0.f, qq = 0.f;
        #pragma unroll
        for (int w = 0; w < 16; w++) { s += redS[w][t]; qq += redQ[w][t]; }
        float mu = s * (1.f / O_);
        float var = qq * (1.f / O_) - mu * mu;
        muS[t] = mu;
        rsS[t] = rsqrtf(var + LN_EPS);
    }
    __syncthreads();
    float mu1[4], rs1[4], mu2[4], rs2[4];
    #pragma unroll
    for (int mt = 0; mt < 4; mt++) {
        mu1[mt] = muS[mt * 16 + g];     rs1[mt] = rsS[mt * 16 + g];
        mu2[mt] = muS[mt * 16 + g + 8]; rs2[mt] = rsS[mt * 16 + g + 8];
    }

    // 4 passes of 128 o-channels each: stage transposed in smem, coalesced store
    #pragma unroll
    for (int p = 0; p < 4; p++) {
        if ((warp >> 2) == p) {
            int obase = (warp & 3) * 32;
            #pragma unroll
            for (int nt = 0; nt < 4; nt++) {
                int ol = obase + nt * 8 + tg * 2;
                int o = p * 128 + ol;
                float2 wv = *(const float2*)&w2g[o];
                float2 bv = *(const float2*)&b2g[o];
                #pragma unroll
                for (int mt = 0; mt < 4; mt++) {
                    int r1 = mt * 16 + g, r2 = r1 + 8;
                    float4 a = acc[mt][nt];
                    sout[ol * 68 + r1]       = (a.x - mu1[mt]) * rs1[mt] * wv.x + bv.x;
                    sout[(ol + 1) * 68 + r1] = (a.y - mu1[mt]) * rs1[mt] * wv.y + bv.y;
                    sout[ol * 68 + r2]       = (a.z - mu2[mt]) * rs2[mt] * wv.x + bv.x;
                    sout[(ol + 1) * 68 + r2] = (a.w - mu2[mt]) * rs2[mt] * wv.y + bv.y;
                }
            }
        }
        __syncthreads();
        #pragma unroll
        for (int i = 0; i < 4; i++) {
            int idx = t + 512 * i;
            int ol = idx >> 4, nn = (idx & 15) * 4;
            float4 v = *(float4*)&sout[ol * 68 + nn];
            *(float4*)&out[((size_t)bb * O_ + p * 128 + ol) * N_ + n0 + nn] = v;
        }
        __syncthreads();
    }
}

// ---------------- launch -----------------------------------------------------
extern "C" void kernel_launch(void* const* d_in, const int* in_sizes, int n_in,
                              void* d_out, int out_size) {
    const float* x1       = (const float*)d_in[0];
    const float* x2       = (const float*)d_in[1];
    const float* norm1_w  = (const float*)d_in[2];
    const float* norm1_b  = (const float*)d_in[3];
    const float* reproj_w = (const float*)d_in[4];
    const float* reproj_b = (const float*)d_in[5];
    const float* norm2_w  = (const float*)d_in[6];
    const float* norm2_b  = (const float*)d_in[7];
    const float* attn_w   = (const float*)d_in[8];
    float* out = (float*)d_out;

    float *n1, *n2, *q, *pM, *pS, *M, *Si, *ctxp, *ctx, *WA;
    cudaGetSymbolAddress((void**)&n1,   g_n1);
    cudaGetSymbolAddress((void**)&n2,   g_n2);
    cudaGetSymbolAddress((void**)&q,    g_q);
    cudaGetSymbolAddress((void**)&pM,   g_pM);
    cudaGetSymbolAddress((void**)&pS,   g_pS);
    cudaGetSymbolAddress((void**)&M,    g_M);
    cudaGetSymbolAddress((void**)&Si,   g_Si);
    cudaGetSymbolAddress((void**)&ctxp, g_ctxp);
    cudaGetSymbolAddress((void**)&ctx,  g_ctx);
    cudaGetSymbolAddress((void**)&WA,   g_WA);

    ln_kernel<<<B_ * N_ / 8, 256>>>(x1, norm1_w, norm1_b, n1, nullptr);
    ln_kernel<<<B_ * N_ / 8, 256>>>(x2, norm1_w, norm1_b, n2, q);

    colstat1<<<dim3(NCH_, B_), 256>>>(n2, pM, pS);
    colstat2<<<B_, 256>>>(pM, pS, M, Si);

    ctx_gemm<<<dim3(2, 2, B_ * KS_), 256>>>(n2, n1, M, ctxp);

    topk_kernel<<<B_ * C_, 256>>>(ctxp, ctx, attn_w, Si);

    gemm64<<<dim3(C_ / 64, O_ / 64, B_), 256>>>(
        reproj_w, ctx, WA, C_,
        (size_t)0, (size_t)C_ * C_, (size_t)O_ * C_,
        C_, C_, C_);

    final_kernel<<<dim3(N_ / 64, B_), 512>>>(q, WA, reproj_b, norm2_w, norm2_b, out);
}

// round 5
// speedup vs baseline: 4.9702x; 1.2683x over previous
#include <cuda_runtime.h>
#include <math.h>

#define B_ 8
#define N_ 9216
#define C_ 256
#define O_ 512
#define KS_ 16
#define CHK_ (N_/KS_)      // 576
#define LN_EPS 1e-5f

typedef unsigned int uint;

// ---------------- scratch ----------------------------------------------------
__device__ float  g_q  [B_*N_*C_];   // channel softmax of LN(x2)
__device__ float  g_qs [B_*N_];      // channel sum-exp per row
__device__ float2 g_st1[B_*N_];      // (mu, rsd) of x1 rows
__device__ float  g_S  [B_*C_];      // N-softmax denom per (b,d)
__device__ float  g_ctxp[(size_t)KS_*B_*C_*C_];
__device__ float  g_ctx[B_*C_*C_];
__device__ float  g_WA [B_*O_*C_];

// ---------------- fast exp (FMA only) ----------------------------------------
__device__ __forceinline__ float fexp(float x) {
    float t = fmaf(x, 1.4426950408889634f, 12582912.0f);
    float n = t - 12582912.0f;
    int ni = __float_as_int(t) - 0x4B400000;
    float r = fmaf(n, -0.693359375f, x);
    r = fmaf(n, 2.12194440e-4f, r);
    float z = r * r;
    float p = 1.9875691500E-4f;
    p = fmaf(p, r, 1.3981999507E-3f);
    p = fmaf(p, r, 8.3334519073E-3f);
    p = fmaf(p, r, 4.1665795894E-2f);
    p = fmaf(p, r, 1.6666665459E-1f);
    p = fmaf(p, r, 5.0000001201E-1f);
    float res = fmaf(z, p, r) + 1.0f;
    res = __int_as_float(__float_as_int(res) + (ni << 23));
    return (x > -80.0f) ? res : 0.0f;
}

// ---------------- tf32 helpers -----------------------------------------------
__device__ __forceinline__ uint tf32c(float f) {
    uint r;
    asm("cvt.rna.tf32.f32 %0, %1;" : "=r"(r) : "f"(f));
    return r;
}
__device__ __forceinline__ uint4 tf32c4(float4 v) {
    uint4 u;
    u.x = tf32c(v.x); u.y = tf32c(v.y); u.z = tf32c(v.z); u.w = tf32c(v.w);
    return u;
}
__device__ __forceinline__ void mma8(float4& d, const uint* a, const uint* b) {
    asm volatile("mma.sync.aligned.m16n8k8.row.col.f32.tf32.tf32.f32 "
        "{%0,%1,%2,%3}, {%4,%5,%6,%7}, {%8,%9}, {%0,%1,%2,%3};"
        : "+f"(d.x), "+f"(d.y), "+f"(d.z), "+f"(d.w)
        : "r"(a[0]), "r"(a[1]), "r"(a[2]), "r"(a[3]), "r"(b[0]), "r"(b[1]));
}

// ---------------- block reductions (256 threads) -----------------------------
__device__ __forceinline__ float blkSum(float v, float* sh) {
    #pragma unroll
    for (int o = 16; o > 0; o >>= 1) v += __shfl_down_sync(0xffffffffu, v, o);
    int w = threadIdx.x >> 5;
    if ((threadIdx.x & 31) == 0) sh[w] = v;
    __syncthreads();
    if (threadIdx.x < 32) {
        float x = (threadIdx.x < 8) ? sh[threadIdx.x] : 0.f;
        #pragma unroll
        for (int o = 4; o > 0; o >>= 1) x += __shfl_down_sync(0xffffffffu, x, o);
        if (threadIdx.x == 0) sh[0] = x;
    }
    __syncthreads();
    float r = sh[0];
    __syncthreads();
    return r;
}
__device__ __forceinline__ float blkMax(float v, float* sh) {
    #pragma unroll
    for (int o = 16; o > 0; o >>= 1) v = fmaxf(v, __shfl_xor_sync(0xffffffffu, v, o));
    int w = threadIdx.x >> 5;
    if ((threadIdx.x & 31) == 0) sh[w] = v;
    __syncthreads();
    if (threadIdx.x < 32) {
        float x = (threadIdx.x < 8) ? sh[threadIdx.x] : -INFINITY;
        #pragma unroll
        for (int o = 4; o > 0; o >>= 1) x = fmaxf(x, __shfl_xor_sync(0xffffffffu, x, o));
        if (threadIdx.x == 0) sh[0] = x;
    }
    __syncthreads();
    float r = sh[0];
    __syncthreads();
    return r;
}

// ---------------- stats of x1 rows (mu, rsd), warp per row -------------------
__global__ void stats_kernel(const float* __restrict__ x, float2* __restrict__ st) {
    int warp = threadIdx.x >> 5, lane = threadIdx.x & 31;
    size_t row = (size_t)blockIdx.x * 8 + warp;
    const float4* xr = (const float4*)(x + row * C_);
    float4 v0 = xr[lane], v1 = xr[lane + 32];
    float s  = v0.x + v0.y + v0.z + v0.w + v1.x + v1.y + v1.z + v1.w;
    float s2 = v0.x*v0.x + v0.y*v0.y + v0.z*v0.z + v0.w*v0.w
             + v1.x*v1.x + v1.y*v1.y + v1.z*v1.z + v1.w*v1.w;
    #pragma unroll
    for (int o = 16; o > 0; o >>= 1) {
        s  += __shfl_xor_sync(0xffffffffu, s, o);
        s2 += __shfl_xor_sync(0xffffffffu, s2, o);
    }
    float mu = s * (1.f / C_);
    float rsd = rsqrtf(s2 * (1.f / C_) - mu * mu + LN_EPS);
    if (lane == 0) st[row] = make_float2(mu, rsd);
}

// ---------------- q kernel: LN(x2) -> channel softmax + row sum --------------
__global__ void q_kernel(const float* __restrict__ x,
                         const float* __restrict__ w,
                         const float* __restrict__ b,
                         float* __restrict__ qout,
                         float* __restrict__ qs) {
    int warp = threadIdx.x >> 5, lane = threadIdx.x & 31;
    size_t row = (size_t)blockIdx.x * 8 + warp;
    const float4* xr = (const float4*)(x + row * C_);
    float4 v0 = xr[lane], v1 = xr[lane + 32];
    float s  = v0.x + v0.y + v0.z + v0.w + v1.x + v1.y + v1.z + v1.w;
    float s2 = v0.x*v0.x + v0.y*v0.y + v0.z*v0.z + v0.w*v0.w
             + v1.x*v1.x + v1.y*v1.y + v1.z*v1.z + v1.w*v1.w;
    #pragma unroll
    for (int o = 16; o > 0; o >>= 1) {
        s  += __shfl_xor_sync(0xffffffffu, s, o);
        s2 += __shfl_xor_sync(0xffffffffu, s2, o);
    }
    float mu = s * (1.f / C_);
    float rsd = rsqrtf(s2 * (1.f / C_) - mu * mu + LN_EPS);
    float4 w0 = ((const float4*)w)[lane], w1 = ((const float4*)w)[lane + 32];
    float4 b0 = ((const float4*)b)[lane], b1 = ((const float4*)b)[lane + 32];
    float4 e0, e1;
    e0.x = fexp((v0.x - mu) * rsd * w0.x + b0.x);
    e0.y = fexp((v0.y - mu) * rsd * w0.y + b0.y);
    e0.z = fexp((v0.z - mu) * rsd * w0.z + b0.z);
    e0.w = fexp((v0.w - mu) * rsd * w0.w + b0.w);
    e1.x = fexp((v1.x - mu) * rsd * w1.x + b1.x);
    e1.y = fexp((v1.y - mu) * rsd * w1.y + b1.y);
    e1.z = fexp((v1.z - mu) * rsd * w1.z + b1.z);
    e1.w = fexp((v1.w - mu) * rsd * w1.w + b1.w);
    float se = e0.x + e0.y + e0.z + e0.w + e1.x + e1.y + e1.z + e1.w;
    #pragma unroll
    for (int o = 16; o > 0; o >>= 1) se += __shfl_xor_sync(0xffffffffu, se, o);
    float inv = 1.f / se;
    e0.x *= inv; e0.y *= inv; e0.z *= inv; e0.w *= inv;
    e1.x *= inv; e1.y *= inv; e1.z *= inv; e1.w *= inv;
    float4* qr = (float4*)(qout + row * C_);
    qr[lane] = e0; qr[lane + 32] = e1;
    if (lane == 0) qs[row] = se;
}

// ---------------- zero S ------------------------------------------------------
__global__ void zero_kernel(float* __restrict__ p, int n) {
    int i = blockIdx.x * 256 + threadIdx.x;
    if (i < n) p[i] = 0.f;
}

// ---------------- context GEMM: prefetch pipeline, fused LN + S accumulation --
__global__ __launch_bounds__(256) void ctx_gemm(
        const float* __restrict__ qg, const float* __restrict__ qsg,
        const float* __restrict__ x1, const float2* __restrict__ st1,
        const float* __restrict__ w1, const float* __restrict__ b1,
        float* __restrict__ ctxp, float* __restrict__ Sg) {
    int bz = blockIdx.z;
    int b = bz / KS_, sk = bz % KS_;
    int m0 = blockIdx.y * 128, n0 = blockIdx.x * 128;
    const float*  A   = qg  + (size_t)b * N_ * C_;
    const float*  Bx  = x1  + (size_t)b * N_ * C_;
    const float*  qsb = qsg + (size_t)b * N_;
    const float2* stb = st1 + (size_t)b * N_;

    __shared__ uint sa[16][136];
    __shared__ uint sb[16][136];
    __shared__ float sW[128], sBb[128];

    int t = threadIdx.x;
    if (t < 128) { sW[t] = w1[n0 + t]; sBb[t] = b1[n0 + t]; }
    int warp = t >> 5, lane = t & 31, g = lane >> 2, tg = lane & 3;
    int wm = (warp >> 2) * 64, wn = (warp & 3) * 32;
    int kk0 = t >> 5, kk1 = 8 + (t >> 5), m4 = (t & 31) * 4;
    bool doS = (blockIdx.x == 0);
    int kbase = sk * CHK_;

    float4 acc[4][4];
    #pragma unroll
    for (int i = 0; i < 4; i++)
        #pragma unroll
        for (int j = 0; j < 4; j++) acc[i][j] = make_float4(0.f, 0.f, 0.f, 0.f);

    float4 a40, a41, b40, b41;
    float aq0, aq1;
    float2 s0, s1;
    float ssum[4] = {0.f, 0.f, 0.f, 0.f};

    auto LOAD = [&](int kt) {
        int r0 = kbase + kt * 16 + kk0, r1 = kbase + kt * 16 + kk1;
        a40 = *(const float4*)&A[(size_t)r0 * C_ + m0 + m4];
        a41 = *(const float4*)&A[(size_t)r1 * C_ + m0 + m4];
        aq0 = qsb[r0]; aq1 = qsb[r1];
        b40 = *(const float4*)&Bx[(size_t)r0 * C_ + n0 + m4];
        b41 = *(const float4*)&Bx[(size_t)r1 * C_ + n0 + m4];
        s0 = stb[r0]; s1 = stb[r1];
    };
    auto STORE = [&]() {
        float4 ea0, ea1;
        ea0.x = a40.x * aq0; ea0.y = a40.y * aq0; ea0.z = a40.z * aq0; ea0.w = a40.w * aq0;
        ea1.x = a41.x * aq1; ea1.y = a41.y * aq1; ea1.z = a41.z * aq1; ea1.w = a41.w * aq1;
        if (doS) {
            ssum[0] += ea0.x + ea1.x; ssum[1] += ea0.y + ea1.y;
            ssum[2] += ea0.z + ea1.z; ssum[3] += ea0.w + ea1.w;
        }
        *(uint4*)&sa[kk0][m4] = tf32c4(ea0);
        *(uint4*)&sa[kk1][m4] = tf32c4(ea1);
        float wv0 = sW[m4], wv1 = sW[m4+1], wv2 = sW[m4+2], wv3 = sW[m4+3];
        float bv0 = sBb[m4], bv1 = sBb[m4+1], bv2 = sBb[m4+2], bv3 = sBb[m4+3];
        float4 l0, l1;
        l0.x = (b40.x - s0.x) * s0.y * wv0 + bv0;
        l0.y = (b40.y - s0.x) * s0.y * wv1 + bv1;
        l0.z = (b40.z - s0.x) * s0.y * wv2 + bv2;
        l0.w = (b40.w - s0.x) * s0.y * wv3 + bv3;
        l1.x = (b41.x - s1.x) * s1.y * wv0 + bv0;
        l1.y = (b41.y - s1.x) * s1.y * wv1 + bv1;
        l1.z = (b41.z - s1.x) * s1.y * wv2 + bv2;
        l1.w = (b41.w - s1.x) * s1.y * wv3 + bv3;
        *(uint4*)&sb[kk0][m4] = tf32c4(l0);
        *(uint4*)&sb[kk1][m4] = tf32c4(l1);
    };

    LOAD(0);
    __syncthreads();   // sW/sBb ready
    STORE();
    __syncthreads();

    for (int kt = 0; kt < CHK_ / 16; kt++) {
        bool last = (kt == CHK_ / 16 - 1);
        if (!last) LOAD(kt + 1);
        #pragma unroll
        for (int ks = 0; ks < 16; ks += 8) {
            uint afr[4][4], bfr[4][2];
            #pragma unroll
            for (int mt = 0; mt < 4; mt++) {
                int m = wm + mt * 16 + g;
                afr[mt][0] = sa[ks + tg][m];
                afr[mt][1] = sa[ks + tg][m + 8];
                afr[mt][2] = sa[ks + tg + 4][m];
                afr[mt][3] = sa[ks + tg + 4][m + 8];
            }
            #pragma unroll
            for (int nt = 0; nt < 4; nt++) {
                int n = wn + nt * 8 + g;
                bfr[nt][0] = sb[ks + tg][n];
                bfr[nt][1] = sb[ks + tg + 4][n];
            }
            #pragma unroll
            for (int mt = 0; mt < 4; mt++)
                #pragma unroll
                for (int nt = 0; nt < 4; nt++)
                    mma8(acc[mt][nt], afr[mt], bfr[nt]);
        }
        __syncthreads();
        if (!last) { STORE(); }
        __syncthreads();
    }

    float* dst = ctxp + ((size_t)sk * B_ + b) * C_ * C_;
    #pragma unroll
    for (int mt = 0; mt < 4; mt++) {
        int row = m0 + wm + mt * 16 + g;
        #pragma unroll
        for (int nt = 0; nt < 4; nt++) {
            int col = n0 + wn + nt * 8 + tg * 2;
            *(float2*)&dst[(size_t)row * C_ + col] = make_float2(acc[mt][nt].x, acc[mt][nt].y);
            *(float2*)&dst[(size_t)(row + 8) * C_ + col] = make_float2(acc[mt][nt].z, acc[mt][nt].w);
        }
    }
    if (doS) {
        #pragma unroll
        for (int j = 0; j < 4; j++)
            atomicAdd(&Sg[b * C_ + m0 + m4 + j], ssum[j]);
    }
}

// ---------------- combined 4-way top-k masked softmax ------------------------
__global__ void topk_kernel(const float* __restrict__ ctxp, float* __restrict__ ctx,
                            const float* __restrict__ aw, const float* __restrict__ Sg) {
    __shared__ float sc[C_];
    __shared__ float sh[8];
    int row = blockIdx.x;
    int b = row >> 8, d = row & 255;
    int t = threadIdx.x;
    float v = 0.f;
    #pragma unroll
    for (int sk = 0; sk < KS_; sk++)
        v += ctxp[(((size_t)sk * B_ + b) * C_ + d) * C_ + t];
    v /= Sg[row];
    sc[t] = v;
    __syncthreads();
    int rank = 0;
    #pragma unroll 8
    for (int f = 0; f < C_; f++) {
        float vf = sc[f];
        rank += (vf > v) || (vf == v && f < t);
    }
    float m = blkMax(v, sh);
    float e = fexp(v - m);
    float z1 = blkSum(rank < 128 ? e : 0.f, sh);
    float z2 = blkSum(rank < 170 ? e : 0.f, sh);
    float z3 = blkSum(rank < 192 ? e : 0.f, sh);
    float z4 = blkSum(rank < 204 ? e : 0.f, sh);
    float coeff = 0.f;
    if (rank < 128) coeff += aw[0] / z1;
    if (rank < 170) coeff += aw[1] / z2;
    if (rank < 192) coeff += aw[2] / z3;
    if (rank < 204) coeff += aw[3] / z4;
    ctx[(size_t)row * C_ + t] = e * coeff;
}

// ---------------- small GEMM (F1): WA = reproj_w @ A -------------------------
__global__ void gemm64(const float* __restrict__ A, const float* __restrict__ B,
                       float* __restrict__ C,
                       int K, size_t sA, size_t sB, size_t sC,
                       int lda, int ldb, int ldc) {
    int bz = blockIdx.z;
    const float* Ab = A + (size_t)bz * sA;
    const float* Bb = B + (size_t)bz * sB;
    float* Cb = C + (size_t)bz * sC;
    int m0 = blockIdx.y * 64, n0 = blockIdx.x * 64;
    __shared__ float sa[16][65];
    __shared__ float sb[16][64];
    int t = threadIdx.x;
    int tx = t % 16, ty = t / 16;
    int r_ld = t / 16, kk_lda = t % 16;
    int c_ld = t % 64, kk_ldb = t / 64;
    float acc[4][4] = {};
    for (int k0 = 0; k0 < K; k0 += 16) {
        __syncthreads();
        #pragma unroll
        for (int it = 0; it < 4; it++) {
            sa[kk_lda][r_ld + 16 * it] = Ab[(size_t)(m0 + r_ld + 16 * it) * lda + k0 + kk_lda];
            sb[kk_ldb + 4 * it][c_ld] = Bb[(size_t)(k0 + kk_ldb + 4 * it) * ldb + n0 + c_ld];
        }
        __syncthreads();
        #pragma unroll
        for (int kk = 0; kk < 16; kk++) {
            float av[4], bv[4];
            #pragma unroll
            for (int i = 0; i < 4; i++) av[i] = sa[kk][ty + 16 * i];
            #pragma unroll
            for (int j = 0; j < 4; j++) bv[j] = sb[kk][tx + 16 * j];
            #pragma unroll
            for (int i = 0; i < 4; i++)
                #pragma unroll
                for (int j = 0; j < 4; j++) acc[i][j] = fmaf(av[i], bv[j], acc[i][j]);
        }
    }
    #pragma unroll
    for (int i = 0; i < 4; i++)
        #pragma unroll
        for (int j = 0; j < 4; j++)
            Cb[(size_t)(m0 + ty + 16 * i) * ldc + n0 + tx + 16 * j] = acc[i][j];
}

// ---------------- final: rp = q @ WA^T (prefetch pipe) + bias -> LN -> NCHW --
#define SQW 12
#define POOLW 10880          // words: max(stage 6912, epilogue 10880)
__global__ __launch_bounds__(512) void final_kernel(
        const float* __restrict__ q, const float* __restrict__ WA,
        const float* __restrict__ rbias, const float* __restrict__ w2g,
        const float* __restrict__ b2g, float* __restrict__ out) {
    __shared__ __align__(16) uint pool[POOLW];
    uint* sq  = pool;             // [64][SQW]
    uint* swa = pool + 64 * SQW;  // [512][SQW]

    int bb = blockIdx.y;
    int n0 = blockIdx.x * 64;
    const float* qb  = q  + (size_t)bb * N_ * C_;
    const float* WAb = WA + (size_t)bb * O_ * C_;

    int t = threadIdx.x, warp = t >> 5, lane = t & 31, g = lane >> 2, tg = lane & 3;
    int o0 = warp * 32;

    int rq = t >> 1, kgq = (t & 1) * 4;          // q loader (t<128)
    int ow0 = t >> 1, kgw0 = (t & 1) * 4;        // WA loader slot 0
    int ow1 = (t + 512) >> 1, kgw1 = ((t + 512) & 1) * 4;

    float4 acc[4][4];
    #pragma unroll
    for (int i = 0; i < 4; i++)
        #pragma unroll
        for (int j = 0; j < 4; j++) acc[i][j] = make_float4(0.f, 0.f, 0.f, 0.f);

    float4 pq, pw0, pw1;
    auto LOAD = [&](int k0) {
        if (t < 128) pq = *(const float4*)&qb[(size_t)(n0 + rq) * C_ + k0 + kgq];
        pw0 = *(const float4*)&WAb[(size_t)ow0 * C_ + k0 + kgw0];
        pw1 = *(const float4*)&WAb[(size_t)ow1 * C_ + k0 + kgw1];
    };
    auto STORE = [&]() {
        if (t < 128) *(uint4*)&sq[rq * SQW + kgq] = tf32c4(pq);
        *(uint4*)&swa[ow0 * SQW + kgw0] = tf32c4(pw0);
        *(uint4*)&swa[ow1 * SQW + kgw1] = tf32c4(pw1);
    };

    LOAD(0); STORE();
    __syncthreads();

    for (int k0 = 0; k0 < C_; k0 += 8) {
        bool last = (k0 == C_ - 8);
        if (!last) LOAD(k0 + 8);
        uint afr[4][4], bfr[4][2];
        #pragma unroll
        for (int mt = 0; mt < 4; mt++) {
            int r1 = mt * 16 + g;
            afr[mt][0] = sq[r1 * SQW + tg];
            afr[mt][1] = sq[(r1 + 8) * SQW + tg];
            afr[mt][2] = sq[r1 * SQW + tg + 4];
            afr[mt][3] = sq[(r1 + 8) * SQW + tg + 4];
        }
        #pragma unroll
        for (int nt = 0; nt < 4; nt++) {
            int o = o0 + nt * 8 + g;
            bfr[nt][0] = swa[o * SQW + tg];
            bfr[nt][1] = swa[o * SQW + tg + 4];
        }
        #pragma unroll
        for (int mt = 0; mt < 4; mt++)
            #pragma unroll
            for (int nt = 0; nt < 4; nt++)
                mma8(acc[mt][nt], afr[mt], bfr[nt]);
        __syncthreads();
        if (!last) { STORE(); }
        __syncthreads();
    }

    // ---- epilogue (pool reused) ----
    float* redS = (float*)pool;            // [16][64]
    float* redQ = (float*)(pool + 1024);   // [16][64]
    float* muS  = (float*)(pool + 2048);   // [64]
    float* rsS  = (float*)(pool + 2112);   // [64]
    float* sout = (float*)(pool + 2176);   // [128][68]

    // bias
    #pragma unroll
    for (int nt = 0; nt < 4; nt++) {
        int o = o0 + nt * 8 + tg * 2;
        float2 rb = *(const float2*)&rbias[o];
        #pragma unroll
        for (int mt = 0; mt < 4; mt++) {
            acc[mt][nt].x += rb.x; acc[mt][nt].y += rb.y;
            acc[mt][nt].z += rb.x; acc[mt][nt].w += rb.y;
        }
    }

    // LN stats
    #pragma unroll
    for (int mt = 0; mt < 4; mt++) {
        float sA = 0.f, qA = 0.f, sB = 0.f, qB = 0.f;
        #pragma unroll
        for (int nt = 0; nt < 4; nt++) {
            float4 a = acc[mt][nt];
            sA += a.x + a.y; qA += a.x * a.x + a.y * a.y;
            sB += a.z + a.w; qB += a.z * a.z + a.w * a.w;
        }
        #pragma unroll
        for (int o = 1; o <= 2; o <<= 1) {
            sA += __shfl_xor_sync(0xffffffffu, sA, o);
            qA += __shfl_xor_sync(0xffffffffu, qA, o);
            sB += __shfl_xor_sync(0xffffffffu, sB, o);
            qB += __shfl_xor_sync(0xffffffffu, qB, o);
        }
        if (tg == 0) {
            redS[warp * 64 + mt * 16 + g] = sA;
            redQ[warp * 64 + mt * 16 + g] = qA;
            redS[warp * 64 + mt * 16 + g + 8] = sB;
            redQ[warp * 64 + mt * 16 + g + 8] = qB;
        }
    }
    __syncthreads();
    if (t < 64) {
        float s = 0.f, qq = 0.f;
        #pragma unroll
        for (int w = 0; w < 16; w++) { s += redS[w * 64 + t]; qq += redQ[w * 64 + t]; }
        float mu = s * (1.f / O_);
        float var = qq * (1.f / O_) - mu * mu;
        muS[t] = mu;
        rsS[t] = rsqrtf(var + LN_EPS);
    }
    __syncthreads();
    float mu1[4], rs1[4], mu2[4], rs2[4];
    #pragma unroll
    for (int mt = 0; mt < 4; mt++) {
        mu1[mt] = muS[mt * 16 + g];     rs1[mt] = rsS[mt * 16 + g];
        mu2[mt] = muS[mt * 16 + g + 8]; rs2[mt] = rsS[mt * 16 + g + 8];
    }
    __syncthreads();   // muS read before sout overwrites nothing (disjoint) — keep for safety

    #pragma unroll
    for (int p = 0; p < 4; p++) {
        if ((warp >> 2) == p) {
            int obase = (warp & 3) * 32;
            #pragma unroll
            for (int nt = 0; nt < 4; nt++) {
                int ol = obase + nt * 8 + tg * 2;
                int o = p * 128 + ol;
                float2 wv = *(const float2*)&w2g[o];
                float2 bv = *(const float2*)&b2g[o];
                #pragma unroll
                for (int mt = 0; mt < 4; mt++) {
                    int r1 = mt * 16 + g, r2 = r1 + 8;
                    float4 a = acc[mt][nt];
                    sout[ol * 68 + r1]       = (a.x - mu1[mt]) * rs1[mt] * wv.x + bv.x;
                    sout[(ol + 1) * 68 + r1] = (a.y - mu1[mt]) * rs1[mt] * wv.y + bv.y;
                    sout[ol * 68 + r2]       = (a.z - mu2[mt]) * rs2[mt] * wv.x + bv.x;
                    sout[(ol + 1) * 68 + r2] = (a.w - mu2[mt]) * rs2[mt] * wv.y + bv.y;
                }
            }
        }
        __syncthreads();
        #pragma unroll
        for (int i = 0; i < 4; i++) {
            int idx = t + 512 * i;
            int ol = idx >> 4, nn = (idx & 15) * 4;
            float4 v = *(float4*)&sout[ol * 68 + nn];
            *(float4*)&out[((size_t)bb * O_ + p * 128 + ol) * N_ + n0 + nn] = v;
        }
        __syncthreads();
    }
}

// ---------------- launch -----------------------------------------------------
extern "C" void kernel_launch(void* const* d_in, const int* in_sizes, int n_in,
                              void* d_out, int out_size) {
    const float* x1       = (const float*)d_in[0];
    const float* x2       = (const float*)d_in[1];
    const float* norm1_w  = (const float*)d_in[2];
    const float* norm1_b  = (const float*)d_in[3];
    const float* reproj_w = (const float*)d_in[4];
    const float* reproj_b = (const float*)d_in[5];
    const float* norm2_w  = (const float*)d_in[6];
    const float* norm2_b  = (const float*)d_in[7];
    const float* attn_w   = (const float*)d_in[8];
    float* out = (float*)d_out;

    float *q, *qs, *S, *ctxp, *ctx, *WA;
    float2* st1;
    cudaGetSymbolAddress((void**)&q,    g_q);
    cudaGetSymbolAddress((void**)&qs,   g_qs);
    cudaGetSymbolAddress((void**)&st1,  g_st1);
    cudaGetSymbolAddress((void**)&S,    g_S);
    cudaGetSymbolAddress((void**)&ctxp, g_ctxp);
    cudaGetSymbolAddress((void**)&ctx,  g_ctx);
    cudaGetSymbolAddress((void**)&WA,   g_WA);

    stats_kernel<<<B_ * N_ / 8, 256>>>(x1, st1);
    q_kernel<<<B_ * N_ / 8, 256>>>(x2, norm1_w, norm1_b, q, qs);
    zero_kernel<<<(B_ * C_ + 255) / 256, 256>>>(S, B_ * C_);

    ctx_gemm<<<dim3(2, 2, B_ * KS_), 256>>>(q, qs, x1, st1, norm1_w, norm1_b, ctxp, S);

    topk_kernel<<<B_ * C_, 256>>>(ctxp, ctx, attn_w, S);

    gemm64<<<dim3(C_ / 64, O_ / 64, B_), 256>>>(
        reproj_w, ctx, WA, C_,
        (size_t)0, (size_t)C_ * C_, (size_t)O_ * C_,
        C_, C_, C_);

    final_kernel<<<dim3(N_ / 64, B_), 512>>>(q, WA, reproj_b, norm2_w, norm2_b, out);
}